// round 1
// baseline (speedup 1.0000x reference)
#include <cuda_runtime.h>

#define NN 4096
#define MM 32
#define NFC 64
#define LOG2F_ 0.693147180559945f

// Scratch (no allocations allowed)
__device__ float g_pre[NN * 256];   // 4 MB
__device__ float g_acc[NN * 704];   // 11.5 MB : S0,S1,U0,U1,U2,T20,T21,T22,T30,T31,T32 (64 ch each)

__device__ __forceinline__ float ssp(float x) {
    // shifted softplus: log(1+exp(x)) - log(2), numerically stable
    return fmaxf(x, 0.f) + __logf(1.f + __expf(-fabsf(x))) - LOG2F_;
}

// ---- packed f32x2 helpers (ptxas never auto-fuses FFMA2) ----
__device__ __forceinline__ unsigned long long pk2(float a, float b) {
    unsigned long long r;
    asm("mov.b64 %0, {%1, %2};" : "=l"(r) : "f"(a), "f"(b));
    return r;
}
__device__ __forceinline__ void upk2(unsigned long long v, float& a, float& b) {
    asm("mov.b64 {%0, %1}, %2;" : "=f"(a), "=f"(b) : "l"(v));
}
__device__ __forceinline__ unsigned long long fma2_(unsigned long long a, unsigned long long b,
                                                    unsigned long long c) {
    unsigned long long r;
    asm("fma.rn.f32x2 %0, %1, %2, %3;" : "=l"(r) : "l"(a), "l"(b), "l"(c));
    return r;
}

// ============================================================
// K1: pre = ielin(feat_in, w_pre0, w_pre1)   (per-node, 16 nodes/block)
// ============================================================
__global__ void __launch_bounds__(256) k_pre(const float* __restrict__ feat,
                                             const float* __restrict__ wp0,
                                             const float* __restrict__ wp1) {
    __shared__ float sw[8192];
    __shared__ float sf[256];
    int t = threadIdx.x;
    for (int i = t; i < 8192; i += 256) sw[i] = (i < 4096) ? wp0[i] : wp1[i - 4096];
    __syncthreads();
    int g = t >> 6, c = t & 63;
    const float* W = (g == 0) ? sw : (sw + 4096);
    for (int n = 0; n < 16; n++) {
        int node = blockIdx.x * 16 + n;
        __syncthreads();
        sf[t] = feat[node * 256 + t];
        __syncthreads();
        const float* fr = sf + g * 64;
        float acc = 0.f;
#pragma unroll
        for (int k = 0; k < 64; k++) acc += fr[k] * W[k * 64 + c];
        g_pre[node * 256 + t] = acc;
    }
}

// ============================================================
// K2: edge kernel. 1 warp = 1 node. 4 warps/block.
//   Phase A (lane = edge): geometry, rbf, h = ssp(rbf @ w_f1) -> smem
//   Phase B (lane = channel pair): fr = h @ w_f2, coupler accumulators -> g_acc
// ============================================================
#define K2_WARPS 4
#define HSTRIDE 65
// dyn smem floats: wf1t 1024 | wf2 4096 | h 4*32*65 | u 4*32*4 | j 128 ints
#define K2_F (1024 + 4096 + K2_WARPS * 32 * HSTRIDE + K2_WARPS * 32 * 4)
#define K2_SMEM (K2_F * 4 + K2_WARPS * 32 * 4)

__global__ void __launch_bounds__(128) k_edge(const float* __restrict__ xyz,
                                              const float* __restrict__ wf1,
                                              const float* __restrict__ wf2,
                                              const int* __restrict__ src,
                                              const int* __restrict__ emask) {
    extern __shared__ float sm[];
    float* s_wf1t = sm;                                   // [k*16+j] transposed
    float* s_wf2 = sm + 1024;                             // [k*64+c]
    float* s_h = sm + 5120;                               // per-warp 32*65
    float* s_u = sm + 5120 + K2_WARPS * 32 * HSTRIDE;     // per-edge (uy,uz,ux,_)
    int* s_j = (int*)(s_u + K2_WARPS * 32 * 4);

    int t = threadIdx.x;
    for (int i = t; i < 4096; i += 128) s_wf2[i] = wf2[i];
    for (int i = t; i < 1024; i += 128) {
        int k = i >> 4, j = i & 15;
        s_wf1t[i] = wf1[j * 64 + k];   // w_f1 is (16,64)
    }
    __syncthreads();

    int w = t >> 5, lane = t & 31;
    int node = blockIdx.x * K2_WARPS + w;
    float* hsh = s_h + w * 32 * HSTRIDE;

    // ---------- Phase A: lane = edge ----------
    unsigned actmask;
    {
        int e = lane;
        int eid = node * MM + e;
        int j = src[eid];
        int mk = emask[eid];
        float pix = xyz[node * 3 + 0], piy = xyz[node * 3 + 1], piz = xyz[node * 3 + 2];
        float rx = xyz[j * 3 + 0] - pix;
        float ry = xyz[j * 3 + 1] - piy;
        float rz = xyz[j * 3 + 2] - piz;
        float d2 = rx * rx + ry * ry + rz * rz;
        float invd = rsqrtf(d2);
        float d = d2 * invd;
        float x = d * 0.2f;
        bool act = (mk != 0) && (x < 1.0f);
        float x2 = x * x, x3 = x2 * x;
        float env = 1.f + x3 * (-10.f + x * (15.f - 6.f * x));
        float scale = env * invd;
        int ub = (w * 32 + e) * 4;
        s_u[ub + 0] = ry * invd;  // u_rsh = (y, z, x)
        s_u[ub + 1] = rz * invd;
        s_u[ub + 2] = rx * invd;
        s_j[w * 32 + e] = j;
        actmask = __ballot_sync(0xffffffffu, act);
        if (act) {
            float rb[16];
#pragma unroll
            for (int q = 0; q < 16; q++) rb[q] = sinf(x * (float)q) * scale;
#pragma unroll 2
            for (int k = 0; k < 64; k++) {
                const float4* wr = (const float4*)(s_wf1t + k * 16);
                float4 w0 = wr[0], w1 = wr[1], w2 = wr[2], w3 = wr[3];
                float a = rb[0] * w0.x + rb[1] * w0.y + rb[2] * w0.z + rb[3] * w0.w;
                a += rb[4] * w1.x + rb[5] * w1.y + rb[6] * w1.z + rb[7] * w1.w;
                a += rb[8] * w2.x + rb[9] * w2.y + rb[10] * w2.z + rb[11] * w2.w;
                a += rb[12] * w3.x + rb[13] * w3.y + rb[14] * w3.z + rb[15] * w3.w;
                hsh[e * HSTRIDE + k] = ssp(a);   // bank-conflict-free (stride 65)
            }
        }
        __syncwarp();
    }

    // ---------- Phase B: lane owns channels (2*lane, 2*lane+1) ----------
    int c0 = lane * 2;
    float S0a = 0, S0b = 0, S1a = 0, S1b = 0;
    float U0a = 0, U0b = 0, U1a = 0, U1b = 0, U2a = 0, U2b = 0;
    float P0a = 0, P0b = 0, P1a = 0, P1b = 0, P2a = 0, P2b = 0;
    float Q0a = 0, Q0b = 0, Q1a = 0, Q1b = 0, Q2a = 0, Q2b = 0;

    unsigned act = actmask;
    while (act) {
        int e = __ffs(act) - 1;
        act &= act - 1;
        int ub = (w * 32 + e) * 4;
        float uy = s_u[ub + 0], uz = s_u[ub + 1], ux = s_u[ub + 2];
        int j = s_j[w * 32 + e];
        const float* pr = g_pre + j * 256 + c0;
        float2 a0 = *(const float2*)(pr);
        float2 ay = *(const float2*)(pr + 64);
        float2 az = *(const float2*)(pr + 128);
        float2 ax = *(const float2*)(pr + 192);

        // fr[c] = sum_k h[k] * w_f2[k][c]  (packed f32x2)
        unsigned long long fr2 = pk2(0.f, 0.f);
        const float* hh = hsh + e * HSTRIDE;
#pragma unroll 8
        for (int k = 0; k < 64; k++) {
            float hk = hh[k];
            unsigned long long wv = *(const unsigned long long*)(s_wf2 + k * 64 + c0);
            fr2 = fma2_(pk2(hk, hk), wv, fr2);
        }
        float fa, fb;
        upk2(fr2, fa, fb);

        // coupler accumulators
        float sa = ay.x * uy + az.x * uz + ax.x * ux;
        float sb = ay.y * uy + az.y * uz + ax.y * ux;
        float t0a = a0.x * fa, t0b = a0.y * fb;
        S0a += t0a;        S0b += t0b;
        S1a += sa * fa;    S1b += sb * fb;
        U0a += uy * t0a;   U0b += uy * t0b;
        U1a += uz * t0a;   U1b += uz * t0b;
        U2a += ux * t0a;   U2b += ux * t0b;
        P0a += ay.x * fa;  P0b += ay.y * fb;
        P1a += az.x * fa;  P1b += az.y * fb;
        P2a += ax.x * fa;  P2b += ax.y * fb;
        // cross(a1, u) in cart, output in rsh order (Cy, Cz, Cx)
        float cya = az.x * ux - ax.x * uz, cyb = az.y * ux - ax.y * uz;
        float cza = ax.x * uy - ay.x * ux, czb = ax.y * uy - ay.y * ux;
        float cxa = ay.x * uz - az.x * uy, cxb = ay.y * uz - az.y * uy;
        Q0a += cya * fa;   Q0b += cyb * fb;
        Q1a += cza * fa;   Q1b += czb * fb;
        Q2a += cxa * fa;   Q2b += cxb * fb;
    }

    float* dst = g_acc + node * 704 + c0;
    *(float2*)(dst + 0)   = make_float2(S0a, S0b);
    *(float2*)(dst + 64)  = make_float2(S1a, S1b);
    *(float2*)(dst + 128) = make_float2(U0a, U0b);
    *(float2*)(dst + 192) = make_float2(U1a, U1b);
    *(float2*)(dst + 256) = make_float2(U2a, U2b);
    *(float2*)(dst + 320) = make_float2(P0a, P0b);
    *(float2*)(dst + 384) = make_float2(P1a, P1b);
    *(float2*)(dst + 448) = make_float2(P2a, P2b);
    *(float2*)(dst + 512) = make_float2(Q0a, Q0b);
    *(float2*)(dst + 576) = make_float2(Q1a, Q1b);
    *(float2*)(dst + 640) = make_float2(Q2a, Q2b);
}

// ============================================================
// K3: per-node hoisted w_a matmuls + gate + w_b ielin + residual
// ============================================================
#define K3_NODES 16
// dyn smem floats: wa0 8192 | wa1 12288 | wb 8192 | acc 704 | agg 256 | gate 128 | gated 256
#define K3_F (8192 + 12288 + 8192 + 704 + 256 + 128 + 256)
#define K3_SMEM (K3_F * 4)

__global__ void __launch_bounds__(256) k_node(const float* __restrict__ feat,
                                              const float* __restrict__ wa0,
                                              const float* __restrict__ wa1,
                                              const float* __restrict__ wb0,
                                              const float* __restrict__ wb1,
                                              float* __restrict__ out) {
    extern __shared__ float sm[];
    float* s_wa0 = sm;             // 8192
    float* s_wa1 = sm + 8192;      // 12288
    float* s_wb = sm + 20480;      // 8192 (wb0 | wb1)
    float* s_acc = sm + 28672;     // 704
    float* s_agg = sm + 29376;     // 256
    float* s_gate = sm + 29632;    // 128
    float* s_gtd = sm + 29760;     // 256

    int t = threadIdx.x;
    for (int i = t; i < 8192; i += 256) s_wa0[i] = wa0[i];
    for (int i = t; i < 12288; i += 256) s_wa1[i] = wa1[i];
    for (int i = t; i < 4096; i += 256) {
        s_wb[i] = wb0[i];
        s_wb[4096 + i] = wb1[i];
    }
    __syncthreads();

    int g = t >> 6, c = t & 63;
    for (int n = 0; n < K3_NODES; n++) {
        int node = blockIdx.x * K3_NODES + n;
        __syncthreads();
        for (int i = t; i < 704; i += 256) s_acc[i] = g_acc[node * 704 + i];
        __syncthreads();

        float a = 0.f;
        if (g == 0) {
#pragma unroll
            for (int k = 0; k < 64; k++)
                a += s_acc[k] * s_wa0[k * 64 + c] + s_acc[64 + k] * s_wa0[(64 + k) * 64 + c];
        } else {
            int m = g - 1;
            const float* u = s_acc + 128 + m * 64;
            const float* p = s_acc + 320 + m * 64;
            const float* q = s_acc + 512 + m * 64;
#pragma unroll
            for (int k = 0; k < 64; k++)
                a += u[k] * s_wa1[k * 64 + c] + p[k] * s_wa1[(64 + k) * 64 + c] +
                     q[k] * s_wa1[(128 + k) * 64 + c];
        }
        s_agg[t] = a;
        __syncthreads();

        if (t < 64) {
            float v1 = s_agg[64 + t], v2 = s_agg[128 + t], v3 = s_agg[192 + t];
            float inv1 = sqrtf(v1 * v1 + v2 * v2 + v3 * v3 + 1e-12f);
            s_gate[t] = ssp(s_agg[t]);
            s_gate[64 + t] = ssp(inv1);
        }
        __syncthreads();
        s_gtd[t] = s_agg[t] * s_gate[(g == 0) ? c : (64 + c)];
        __syncthreads();

        float o = 0.f;
        const float* gg = s_gtd + g * 64;
        const float* W = (g == 0) ? s_wb : (s_wb + 4096);
#pragma unroll
        for (int k = 0; k < 64; k++) o += gg[k] * W[k * 64 + c];
        out[node * 256 + t] = feat[node * 256 + t] + o;
    }
}

// ============================================================
extern "C" void kernel_launch(void* const* d_in, const int* in_sizes, int n_in,
                              void* d_out, int out_size) {
    const float* xyz = (const float*)d_in[0];
    const float* feat = (const float*)d_in[1];
    const float* wf1 = (const float*)d_in[2];
    const float* wf2 = (const float*)d_in[3];
    const float* wp0 = (const float*)d_in[4];
    const float* wp1 = (const float*)d_in[5];
    const float* wa0 = (const float*)d_in[6];
    const float* wa1 = (const float*)d_in[7];
    const float* wb0 = (const float*)d_in[8];
    const float* wb1 = (const float*)d_in[9];
    const int* src = (const int*)d_in[10];
    const int* emask = (const int*)d_in[11];
    float* out = (float*)d_out;

    cudaFuncSetAttribute(k_edge, cudaFuncAttributeMaxDynamicSharedMemorySize, K2_SMEM);
    cudaFuncSetAttribute(k_node, cudaFuncAttributeMaxDynamicSharedMemorySize, K3_SMEM);

    k_pre<<<NN / 16, 256>>>(feat, wp0, wp1);
    k_edge<<<NN / K2_WARPS, 128, K2_SMEM>>>(xyz, wf1, wf2, src, emask);
    k_node<<<NN / K3_NODES, 256, K3_SMEM>>>(feat, wa0, wa1, wb0, wb1, out);
}

// round 2
// speedup vs baseline: 1.2927x; 1.2927x over previous
#include <cuda_runtime.h>

#define NN 4096
#define MM 32
#define LOG2F_ 0.693147180559945f
#define HSTRIDE 65

typedef unsigned long long u64;

// ---- scratch globals (no allocations allowed) ----
__device__ float g_pre[NN * 256];        // 4 MB
__device__ float g_fr[NN * MM * 64];     // 33.5 MB
__device__ float4 g_u[NN * MM];          // 2 MB  (uy, uz, ux, active)
__device__ float g_acc[NN * 704];        // 11.5 MB
__device__ float g_gtd[NN * 256];        // 4 MB

__device__ __forceinline__ float ssp(float x) {
    return fmaxf(x, 0.f) + __logf(1.f + __expf(-fabsf(x))) - LOG2F_;
}
__device__ __forceinline__ u64 pk2(float a, float b) {
    u64 r; asm("mov.b64 %0, {%1, %2};" : "=l"(r) : "f"(a), "f"(b)); return r;
}
__device__ __forceinline__ void upk2(u64 v, float& a, float& b) {
    asm("mov.b64 {%0, %1}, %2;" : "=f"(a), "=f"(b) : "l"(v));
}
__device__ __forceinline__ u64 fma2_(u64 a, u64 b, u64 c) {
    u64 r; asm("fma.rn.f32x2 %0, %1, %2, %3;" : "=l"(r) : "l"(a), "l"(b), "l"(c)); return r;
}

// ============================================================
// K1: pre = ielin(feat, wp0, wp1). 8 nodes/block (2 concurrent), fma2, split-k.
// ============================================================
__global__ void __launch_bounds__(256) k_pre(const float* __restrict__ feat,
                                             const float* __restrict__ wp0,
                                             const float* __restrict__ wp1) {
    __shared__ float sw[8192];
    __shared__ float sf[512];
    int t = threadIdx.x;
    for (int i = t; i < 1024; i += 256) ((float4*)sw)[i] = ((const float4*)wp0)[i];
    for (int i = t; i < 1024; i += 256) ((float4*)(sw + 4096))[i] = ((const float4*)wp1)[i];
    __syncthreads();
    int sub = t >> 7, tt = t & 127, g = tt >> 5, c0 = (tt & 31) * 2;
    const float* W = (g == 0) ? sw : (sw + 4096);
    for (int np = 0; np < 4; np++) {
        int base = blockIdx.x * 8 + np * 2;
        __syncthreads();
        sf[t] = feat[base * 256 + t];
        sf[256 + t] = feat[base * 256 + 256 + t];
        __syncthreads();
        const float* f = sf + sub * 256 + g * 64;
        u64 A = pk2(0.f, 0.f), B = pk2(0.f, 0.f);
#pragma unroll 8
        for (int k = 0; k < 32; k++) {
            A = fma2_(pk2(f[k], f[k]), *(const u64*)(W + k * 64 + c0), A);
            B = fma2_(pk2(f[32 + k], f[32 + k]), *(const u64*)(W + (32 + k) * 64 + c0), B);
        }
        float a1, a2, b1, b2; upk2(A, a1, a2); upk2(B, b1, b2);
        int node = base + sub;
        *(float2*)(g_pre + node * 256 + g * 64 + c0) = make_float2(a1 + b1, a2 + b2);
    }
}

// ============================================================
// K2: radial filter fr for all active edges. warp = node.
//   Phase A (lane=edge): geometry -> g_u ; h = ssp(rbf @ wf1) -> smem
//   Phase B (lane=channel-pair): fr = h @ wf2, 2 edges per iter, -> g_fr
// ============================================================
#define KF_WARPS 4
#define KF_F (1024 + 4096 + KF_WARPS * 32 * HSTRIDE)
#define KF_SMEM (KF_F * 4)

__global__ void __launch_bounds__(128) k_filt(const float* __restrict__ xyz,
                                              const float* __restrict__ wf1,
                                              const float* __restrict__ wf2,
                                              const int* __restrict__ src,
                                              const int* __restrict__ emask) {
    extern __shared__ float sm[];
    float* s_wf1t = sm;            // [k*16+j] transposed
    float* s_wf2 = sm + 1024;      // [k*64+c]
    float* s_h = sm + 5120;        // per-warp 32*65

    int t = threadIdx.x;
    for (int i = t; i < 1024; i += 128) ((float4*)s_wf2)[i] = ((const float4*)wf2)[i];
    for (int i = t; i < 1024; i += 128) {
        int k = i >> 4, j = i & 15;
        s_wf1t[i] = wf1[j * 64 + k];
    }
    __syncthreads();

    int w = t >> 5, lane = t & 31;
    int node = blockIdx.x * KF_WARPS + w;
    float* hsh = s_h + w * 32 * HSTRIDE;

    // ---------- Phase A ----------
    unsigned actmask;
    {
        int eid = node * MM + lane;
        int mk = emask[eid];
        int j = src[eid];
        float rx = xyz[j * 3 + 0] - xyz[node * 3 + 0];
        float ry = xyz[j * 3 + 1] - xyz[node * 3 + 1];
        float rz = xyz[j * 3 + 2] - xyz[node * 3 + 2];
        float d2 = rx * rx + ry * ry + rz * rz;
        float invd = rsqrtf(d2);
        float d = d2 * invd;
        float x = d * 0.2f;
        bool act = (mk != 0) && (x < 1.0f);
        float x3 = x * x * x;
        float env = 1.f + x3 * (-10.f + x * (15.f - 6.f * x));
        float scale = env * invd;
        g_u[eid] = make_float4(ry * invd, rz * invd, rx * invd, act ? 1.f : 0.f);
        actmask = __ballot_sync(0xffffffffu, act);
        if (act) {
            float rb[16];
#pragma unroll
            for (int q = 0; q < 16; q++) rb[q] = sinf(x * (float)q) * scale;
#pragma unroll 4
            for (int k = 0; k < 64; k++) {
                const float4* wr = (const float4*)(s_wf1t + k * 16);
                float4 w0 = wr[0], w1 = wr[1], w2 = wr[2], w3 = wr[3];
                float a = rb[0] * w0.x + rb[1] * w0.y + rb[2] * w0.z + rb[3] * w0.w;
                a += rb[4] * w1.x + rb[5] * w1.y + rb[6] * w1.z + rb[7] * w1.w;
                a += rb[8] * w2.x + rb[9] * w2.y + rb[10] * w2.z + rb[11] * w2.w;
                a += rb[12] * w3.x + rb[13] * w3.y + rb[14] * w3.z + rb[15] * w3.w;
                hsh[lane * HSTRIDE + k] = ssp(a);
            }
        }
        __syncwarp();
    }

    // ---------- Phase B: 2 edges per iteration (2 independent FMA chains) ----------
    int c0 = lane * 2;
    unsigned a = actmask;
    while (a) {
        int e0 = __ffs(a) - 1; a &= a - 1;
        bool two = false; int e1 = e0;
        if (a) { e1 = __ffs(a) - 1; a &= a - 1; two = true; }
        const float* h0 = hsh + e0 * HSTRIDE;
        const float* h1 = hsh + e1 * HSTRIDE;
        u64 F0 = pk2(0.f, 0.f), F1 = pk2(0.f, 0.f);
#pragma unroll 8
        for (int k = 0; k < 64; k++) {
            u64 wv = *(const u64*)(s_wf2 + k * 64 + c0);
            float a0 = h0[k], a1v = h1[k];
            F0 = fma2_(pk2(a0, a0), wv, F0);
            F1 = fma2_(pk2(a1v, a1v), wv, F1);
        }
        *(u64*)(g_fr + (node * 32 + e0) * 64 + c0) = F0;
        if (two) *(u64*)(g_fr + (node * 32 + e1) * 64 + c0) = F1;
    }
}

// ============================================================
// K3: coupling + edge-sum accumulators. warp = node, lane = channel pair.
//   High occupancy (tiny smem); 2 edges per iter -> ~10 LDG.64 in flight.
// ============================================================
#define KC_WARPS 4
__global__ void __launch_bounds__(128) k_coup(const int* __restrict__ src) {
    __shared__ float4 s_u[KC_WARPS * 32];
    __shared__ int s_j[KC_WARPS * 32];
    int t = threadIdx.x, w = t >> 5, lane = t & 31;
    int node = blockIdx.x * KC_WARPS + w;
    int eid = node * MM + lane;
    float4 u4 = g_u[eid];
    s_u[w * 32 + lane] = u4;
    s_j[w * 32 + lane] = src[eid];
    unsigned actmask = __ballot_sync(0xffffffffu, u4.w != 0.f);
    __syncwarp();

    int c0 = lane * 2;
    float S0a = 0, S0b = 0, S1a = 0, S1b = 0;
    float U0a = 0, U0b = 0, U1a = 0, U1b = 0, U2a = 0, U2b = 0;
    float P0a = 0, P0b = 0, P1a = 0, P1b = 0, P2a = 0, P2b = 0;
    float Q0a = 0, Q0b = 0, Q1a = 0, Q1b = 0, Q2a = 0, Q2b = 0;

    unsigned a = actmask;
    while (a) {
        int e0 = __ffs(a) - 1; a &= a - 1;
        bool two = false; int e1 = e0;
        if (a) { e1 = __ffs(a) - 1; a &= a - 1; two = true; }

        float4 u0 = s_u[w * 32 + e0], u1 = s_u[w * 32 + e1];
        int j0 = s_j[w * 32 + e0], j1 = s_j[w * 32 + e1];
        const float* p0 = g_pre + j0 * 256 + c0;
        const float* p1 = g_pre + j1 * 256 + c0;
        float2 A00 = *(const float2*)(p0);
        float2 A0y = *(const float2*)(p0 + 64);
        float2 A0z = *(const float2*)(p0 + 128);
        float2 A0x = *(const float2*)(p0 + 192);
        float2 B00 = *(const float2*)(p1);
        float2 B0y = *(const float2*)(p1 + 64);
        float2 B0z = *(const float2*)(p1 + 128);
        float2 B0x = *(const float2*)(p1 + 192);
        float2 F0 = *(const float2*)(g_fr + (node * 32 + e0) * 64 + c0);
        float2 F1 = *(const float2*)(g_fr + (node * 32 + e1) * 64 + c0);
        if (!two) { F1.x = 0.f; F1.y = 0.f; }

        // edge 0
        {
            float uy = u0.x, uz = u0.y, ux = u0.z, fa = F0.x, fb = F0.y;
            float sa = A0y.x * uy + A0z.x * uz + A0x.x * ux;
            float sb = A0y.y * uy + A0z.y * uz + A0x.y * ux;
            float t0a = A00.x * fa, t0b = A00.y * fb;
            S0a += t0a;       S0b += t0b;
            S1a += sa * fa;   S1b += sb * fb;
            U0a += uy * t0a;  U0b += uy * t0b;
            U1a += uz * t0a;  U1b += uz * t0b;
            U2a += ux * t0a;  U2b += ux * t0b;
            P0a += A0y.x * fa; P0b += A0y.y * fb;
            P1a += A0z.x * fa; P1b += A0z.y * fb;
            P2a += A0x.x * fa; P2b += A0x.y * fb;
            float cya = A0z.x * ux - A0x.x * uz, cyb = A0z.y * ux - A0x.y * uz;
            float cza = A0x.x * uy - A0y.x * ux, czb = A0x.y * uy - A0y.y * ux;
            float cxa = A0y.x * uz - A0z.x * uy, cxb = A0y.y * uz - A0z.y * uy;
            Q0a += cya * fa;  Q0b += cyb * fb;
            Q1a += cza * fa;  Q1b += czb * fb;
            Q2a += cxa * fa;  Q2b += cxb * fb;
        }
        // edge 1 (zeroed fr when absent)
        {
            float uy = u1.x, uz = u1.y, ux = u1.z, fa = F1.x, fb = F1.y;
            float sa = B0y.x * uy + B0z.x * uz + B0x.x * ux;
            float sb = B0y.y * uy + B0z.y * uz + B0x.y * ux;
            float t0a = B00.x * fa, t0b = B00.y * fb;
            S0a += t0a;       S0b += t0b;
            S1a += sa * fa;   S1b += sb * fb;
            U0a += uy * t0a;  U0b += uy * t0b;
            U1a += uz * t0a;  U1b += uz * t0b;
            U2a += ux * t0a;  U2b += ux * t0b;
            P0a += B0y.x * fa; P0b += B0y.y * fb;
            P1a += B0z.x * fa; P1b += B0z.y * fb;
            P2a += B0x.x * fa; P2b += B0x.y * fb;
            float cya = B0z.x * ux - B0x.x * uz, cyb = B0z.y * ux - B0x.y * uz;
            float cza = B0x.x * uy - B0y.x * ux, czb = B0x.y * uy - B0y.y * ux;
            float cxa = B0y.x * uz - B0z.x * uy, cxb = B0y.y * uz - B0z.y * uy;
            Q0a += cya * fa;  Q0b += cyb * fb;
            Q1a += cza * fa;  Q1b += czb * fb;
            Q2a += cxa * fa;  Q2b += cxb * fb;
        }
    }

    float* dst = g_acc + node * 704 + c0;
    *(float2*)(dst + 0)   = make_float2(S0a, S0b);
    *(float2*)(dst + 64)  = make_float2(S1a, S1b);
    *(float2*)(dst + 128) = make_float2(U0a, U0b);
    *(float2*)(dst + 192) = make_float2(U1a, U1b);
    *(float2*)(dst + 256) = make_float2(U2a, U2b);
    *(float2*)(dst + 320) = make_float2(P0a, P0b);
    *(float2*)(dst + 384) = make_float2(P1a, P1b);
    *(float2*)(dst + 448) = make_float2(P2a, P2b);
    *(float2*)(dst + 512) = make_float2(Q0a, Q0b);
    *(float2*)(dst + 576) = make_float2(Q1a, Q1b);
    *(float2*)(dst + 640) = make_float2(Q2a, Q2b);
}

// ============================================================
// K4: hoisted w_a matmuls + gate -> g_gtd.  128 threads, fma2.
// ============================================================
#define KA_F (8192 + 12288 + 704 + 256 + 128)
#define KA_SMEM (KA_F * 4)
__global__ void __launch_bounds__(128) k_agg(const float* __restrict__ wa0,
                                             const float* __restrict__ wa1) {
    extern __shared__ float sm[];
    float* s_wa0 = sm;            // 8192
    float* s_wa1 = sm + 8192;     // 12288
    float* s_acc = sm + 20480;    // 704
    float* s_agg = sm + 21184;    // 256
    float* s_gate = sm + 21440;   // 128
    int t = threadIdx.x;
    for (int i = t; i < 2048; i += 128) ((float4*)s_wa0)[i] = ((const float4*)wa0)[i];
    for (int i = t; i < 3072; i += 128) ((float4*)s_wa1)[i] = ((const float4*)wa1)[i];
    __syncthreads();

    int g = t >> 5, c0 = (t & 31) * 2;
    for (int n = 0; n < 16; n++) {
        int node = blockIdx.x * 16 + n;
        __syncthreads();
        for (int i = t; i < 704; i += 128) s_acc[i] = g_acc[node * 704 + i];
        __syncthreads();

        float ra, rb;
        if (g == 0) {
            u64 A = pk2(0.f, 0.f), B = pk2(0.f, 0.f);
#pragma unroll 8
            for (int k = 0; k < 64; k++) {
                float s0 = s_acc[k], s1 = s_acc[64 + k];
                A = fma2_(pk2(s0, s0), *(const u64*)(s_wa0 + k * 64 + c0), A);
                B = fma2_(pk2(s1, s1), *(const u64*)(s_wa0 + (64 + k) * 64 + c0), B);
            }
            float a1, a2, b1, b2; upk2(A, a1, a2); upk2(B, b1, b2);
            ra = a1 + b1; rb = a2 + b2;
        } else {
            int m = g - 1;
            const float* U = s_acc + 128 + m * 64;
            const float* P = s_acc + 320 + m * 64;
            const float* Q = s_acc + 512 + m * 64;
            u64 A = pk2(0.f, 0.f), B = pk2(0.f, 0.f), C = pk2(0.f, 0.f);
#pragma unroll 4
            for (int k = 0; k < 64; k++) {
                float uu = U[k], pp = P[k], qq = Q[k];
                A = fma2_(pk2(uu, uu), *(const u64*)(s_wa1 + k * 64 + c0), A);
                B = fma2_(pk2(pp, pp), *(const u64*)(s_wa1 + (64 + k) * 64 + c0), B);
                C = fma2_(pk2(qq, qq), *(const u64*)(s_wa1 + (128 + k) * 64 + c0), C);
            }
            float a1, a2, b1, b2, c1, c2;
            upk2(A, a1, a2); upk2(B, b1, b2); upk2(C, c1, c2);
            ra = a1 + b1 + c1; rb = a2 + b2 + c2;
        }
        s_agg[g * 64 + c0] = ra;
        s_agg[g * 64 + c0 + 1] = rb;
        __syncthreads();
        if (t < 64) {
            float v1 = s_agg[64 + t], v2 = s_agg[128 + t], v3 = s_agg[192 + t];
            s_gate[t] = ssp(s_agg[t]);
            s_gate[64 + t] = ssp(sqrtf(v1 * v1 + v2 * v2 + v3 * v3 + 1e-12f));
        }
        __syncthreads();
        int gi = (g == 0) ? c0 : (64 + c0);
        float2 o;
        o.x = s_agg[g * 64 + c0] * s_gate[gi];
        o.y = s_agg[g * 64 + c0 + 1] * s_gate[gi + 1];
        *(float2*)(g_gtd + node * 256 + g * 64 + c0) = o;
    }
}

// ============================================================
// K5: out = feat + ielin(gtd, wb0, wb1).  Same shape as k_pre.
// ============================================================
__global__ void __launch_bounds__(256) k_final(const float* __restrict__ feat,
                                               const float* __restrict__ wb0,
                                               const float* __restrict__ wb1,
                                               float* __restrict__ out) {
    __shared__ float sw[8192];
    __shared__ float sf[512];
    int t = threadIdx.x;
    for (int i = t; i < 1024; i += 256) ((float4*)sw)[i] = ((const float4*)wb0)[i];
    for (int i = t; i < 1024; i += 256) ((float4*)(sw + 4096))[i] = ((const float4*)wb1)[i];
    __syncthreads();
    int sub = t >> 7, tt = t & 127, g = tt >> 5, c0 = (tt & 31) * 2;
    const float* W = (g == 0) ? sw : (sw + 4096);
    for (int np = 0; np < 4; np++) {
        int base = blockIdx.x * 8 + np * 2;
        __syncthreads();
        sf[t] = g_gtd[base * 256 + t];
        sf[256 + t] = g_gtd[base * 256 + 256 + t];
        __syncthreads();
        const float* f = sf + sub * 256 + g * 64;
        u64 A = pk2(0.f, 0.f), B = pk2(0.f, 0.f);
#pragma unroll 8
        for (int k = 0; k < 32; k++) {
            A = fma2_(pk2(f[k], f[k]), *(const u64*)(W + k * 64 + c0), A);
            B = fma2_(pk2(f[32 + k], f[32 + k]), *(const u64*)(W + (32 + k) * 64 + c0), B);
        }
        float a1, a2, b1, b2; upk2(A, a1, a2); upk2(B, b1, b2);
        int node = base + sub;
        int oi = node * 256 + g * 64 + c0;
        float2 r;
        r.x = feat[oi] + a1 + b1;
        r.y = feat[oi + 1] + a2 + b2;
        *(float2*)(out + oi) = r;
    }
}

// ============================================================
extern "C" void kernel_launch(void* const* d_in, const int* in_sizes, int n_in,
                              void* d_out, int out_size) {
    const float* xyz = (const float*)d_in[0];
    const float* feat = (const float*)d_in[1];
    const float* wf1 = (const float*)d_in[2];
    const float* wf2 = (const float*)d_in[3];
    const float* wp0 = (const float*)d_in[4];
    const float* wp1 = (const float*)d_in[5];
    const float* wa0 = (const float*)d_in[6];
    const float* wa1 = (const float*)d_in[7];
    const float* wb0 = (const float*)d_in[8];
    const float* wb1 = (const float*)d_in[9];
    const int* src = (const int*)d_in[10];
    const int* emask = (const int*)d_in[11];
    float* out = (float*)d_out;

    cudaFuncSetAttribute(k_filt, cudaFuncAttributeMaxDynamicSharedMemorySize, KF_SMEM);
    cudaFuncSetAttribute(k_agg, cudaFuncAttributeMaxDynamicSharedMemorySize, KA_SMEM);

    k_pre<<<NN / 8, 256>>>(feat, wp0, wp1);
    k_filt<<<NN / KF_WARPS, 128, KF_SMEM>>>(xyz, wf1, wf2, src, emask);
    k_coup<<<NN / KC_WARPS, 128>>>(src);
    k_agg<<<NN / 16, 128, KA_SMEM>>>(wa0, wa1);
    k_final<<<NN / 8, 256>>>(feat, wb0, wb1, out);
}

// round 3
// speedup vs baseline: 2.1728x; 1.6808x over previous
#include <cuda_runtime.h>

#define NN 4096
#define MM 32
#define LOG2F_ 0.693147180559945f

typedef unsigned long long u64;

// ---- scratch globals ----
__device__ float g_pre[NN * 256];     // ielin(feat) per node
__device__ float g_fr[NN * MM * 64];  // radial filters, rank-compacted per node
__device__ float4 g_u[NN * MM];       // (uy,uz,ux, j-as-float), rank-compacted
__device__ int g_nact[NN];            // active edge count per node
__device__ float g_acc[NN * 704];     // coupling accumulators
__device__ float g_agg[NN * 256];     // post-w_a aggregate

__device__ __forceinline__ float ssp(float x) {
    return fmaxf(x, 0.f) + __logf(1.f + __expf(-fabsf(x))) - LOG2F_;
}
__device__ __forceinline__ u64 pk2(float a, float b) {
    u64 r; asm("mov.b64 %0, {%1, %2};" : "=l"(r) : "f"(a), "f"(b)); return r;
}
__device__ __forceinline__ void upk2(u64 v, float& a, float& b) {
    asm("mov.b64 {%0, %1}, %2;" : "=f"(a), "=f"(b) : "l"(v));
}
__device__ __forceinline__ u64 fma2_(u64 a, u64 b, u64 c) {
    u64 r; asm("fma.rn.f32x2 %0, %1, %2, %3;" : "=l"(r) : "l"(a), "l"(b), "l"(c)); return r;
}

// ============================================================
// K1: g_pre = ielin(feat, wp0, wp1).  GEMM-tiled: 64 rows (16 nodes x 4 groups),
//     rows viewed as feat(16384,64). Thread: 8 rows x 2 cols.
// ============================================================
#define KP_SMEM ((8192 + 64 * 68) * 4)
__global__ void __launch_bounds__(256) k_pre(const float* __restrict__ feat,
                                             const float* __restrict__ wp0,
                                             const float* __restrict__ wp1) {
    extern __shared__ float sm[];
    float* sW0 = sm;
    float* sW1 = sm + 4096;
    float* sAt = sm + 8192;  // [k][row], stride 68
    int t = threadIdx.x;
    for (int i = t; i < 1024; i += 256) ((float4*)sW0)[i] = ((const float4*)wp0)[i];
    for (int i = t; i < 1024; i += 256) ((float4*)sW1)[i] = ((const float4*)wp1)[i];
    const float4* src = (const float4*)feat + blockIdx.x * 1024;
#pragma unroll
    for (int jj = 0; jj < 4; jj++) {
        int idx = t + jj * 256;
        float4 v = src[idx];
        int d = idx * 4, r = d >> 6, k0 = d & 63;
        sAt[(k0 + 0) * 68 + r] = v.x;
        sAt[(k0 + 1) * 68 + r] = v.y;
        sAt[(k0 + 2) * 68 + r] = v.z;
        sAt[(k0 + 3) * 68 + r] = v.w;
    }
    __syncthreads();
    int rg = t >> 5, c0 = (t & 31) * 2;
    u64 acc[8];
#pragma unroll
    for (int j = 0; j < 8; j++) acc[j] = pk2(0.f, 0.f);
#pragma unroll 4
    for (int k = 0; k < 64; k++) {
        float4 a0 = *(const float4*)(sAt + k * 68 + rg * 8);
        float4 a1 = *(const float4*)(sAt + k * 68 + rg * 8 + 4);
        u64 w0 = *(const u64*)(sW0 + k * 64 + c0);
        u64 w1 = *(const u64*)(sW1 + k * 64 + c0);
        acc[0] = fma2_(pk2(a0.x, a0.x), w0, acc[0]);
        acc[1] = fma2_(pk2(a0.y, a0.y), w1, acc[1]);
        acc[2] = fma2_(pk2(a0.z, a0.z), w1, acc[2]);
        acc[3] = fma2_(pk2(a0.w, a0.w), w1, acc[3]);
        acc[4] = fma2_(pk2(a1.x, a1.x), w0, acc[4]);
        acc[5] = fma2_(pk2(a1.y, a1.y), w1, acc[5]);
        acc[6] = fma2_(pk2(a1.z, a1.z), w1, acc[6]);
        acc[7] = fma2_(pk2(a1.w, a1.w), w1, acc[7]);
    }
#pragma unroll
    for (int j = 0; j < 8; j++) {
        int r = rg * 8 + j;
        *(u64*)(g_pre + blockIdx.x * 4096 + r * 64 + c0) = acc[j];
    }
}

// ============================================================
// K2: radial filters, compacted. warp = node.
// ============================================================
#define KF_WARPS 4
#define KF_PW (16 * 36 + 64 * 36)
#define KF_SMEM ((1024 + 4096 + KF_WARPS * KF_PW) * 4)
__global__ void __launch_bounds__(128) k_filt(const float* __restrict__ xyz,
                                              const float* __restrict__ wf1,
                                              const float* __restrict__ wf2,
                                              const int* __restrict__ src,
                                              const int* __restrict__ emask) {
    extern __shared__ float sm[];
    float* sW1 = sm;        // wf1 [16][64]
    float* sW2 = sm + 1024; // wf2 [64][64]
    int t = threadIdx.x, w = t >> 5, lane = t & 31;
    for (int i = t; i < 256; i += 128) ((float4*)sW1)[i] = ((const float4*)wf1)[i];
    for (int i = t; i < 1024; i += 128) ((float4*)sW2)[i] = ((const float4*)wf2)[i];
    float* sRB = sm + 5120 + w * KF_PW;  // [j16][36] rank-compacted
    float* sH = sRB + 16 * 36;           // [k64][36] rank-compacted
    __syncthreads();

    int node = blockIdx.x * KF_WARPS + w;
    // ---- phase A: lane = edge ----
    int eid = node * MM + lane;
    int mk = emask[eid];
    int j = src[eid];
    float nx = xyz[node * 3], ny = xyz[node * 3 + 1], nz = xyz[node * 3 + 2];
    float rx = xyz[j * 3] - nx, ry = xyz[j * 3 + 1] - ny, rz = xyz[j * 3 + 2] - nz;
    float d2 = rx * rx + ry * ry + rz * rz;
    float invd = rsqrtf(d2);
    float x = d2 * invd * 0.2f;
    bool act = (mk != 0) && (x < 1.f);
    unsigned actmask = __ballot_sync(0xffffffffu, act);
    int nact = __popc(actmask);
    int rank = __popc(actmask & ((1u << lane) - 1u));
    if (lane == 0) g_nact[node] = nact;
    if (act) {
        float x3 = x * x * x;
        float env = 1.f + x3 * (-10.f + x * (15.f - 6.f * x));
        float scale = env * invd;
        g_u[node * MM + rank] = make_float4(ry * invd, rz * invd, rx * invd, __int_as_float(j));
#pragma unroll
        for (int q = 0; q < 16; q++) sRB[q * 36 + rank] = __sinf(x * (float)q) * scale;
    }
    __syncwarp();

    // ---- phase B: lane = k-pair / c-pair; 4 compacted edges per iter ----
    int k0 = lane * 2;
    for (int r0 = 0; r0 < nact; r0 += 4) {
        u64 H0 = pk2(0.f, 0.f), H1 = H0, H2 = H0, H3 = H0;
#pragma unroll
        for (int q = 0; q < 16; q++) {
            float4 rb4 = *(const float4*)(sRB + q * 36 + r0);
            u64 wv = *(const u64*)(sW1 + q * 64 + k0);
            H0 = fma2_(pk2(rb4.x, rb4.x), wv, H0);
            H1 = fma2_(pk2(rb4.y, rb4.y), wv, H1);
            H2 = fma2_(pk2(rb4.z, rb4.z), wv, H2);
            H3 = fma2_(pk2(rb4.w, rb4.w), wv, H3);
        }
        float ha, hb;
        upk2(H0, ha, hb); sH[k0 * 36 + r0] = ssp(ha);     sH[(k0 + 1) * 36 + r0] = ssp(hb);
        upk2(H1, ha, hb); sH[k0 * 36 + r0 + 1] = ssp(ha); sH[(k0 + 1) * 36 + r0 + 1] = ssp(hb);
        upk2(H2, ha, hb); sH[k0 * 36 + r0 + 2] = ssp(ha); sH[(k0 + 1) * 36 + r0 + 2] = ssp(hb);
        upk2(H3, ha, hb); sH[k0 * 36 + r0 + 3] = ssp(ha); sH[(k0 + 1) * 36 + r0 + 3] = ssp(hb);
        __syncwarp();
        u64 F0 = pk2(0.f, 0.f), F1 = F0, F2 = F0, F3 = F0;
#pragma unroll 8
        for (int k = 0; k < 64; k++) {
            float4 h4 = *(const float4*)(sH + k * 36 + r0);
            u64 wv = *(const u64*)(sW2 + k * 64 + k0);
            F0 = fma2_(pk2(h4.x, h4.x), wv, F0);
            F1 = fma2_(pk2(h4.y, h4.y), wv, F1);
            F2 = fma2_(pk2(h4.z, h4.z), wv, F2);
            F3 = fma2_(pk2(h4.w, h4.w), wv, F3);
        }
        float* fb = g_fr + (node * MM + r0) * 64 + k0;
        *(u64*)(fb) = F0;
        *(u64*)(fb + 64) = F1;
        *(u64*)(fb + 128) = F2;
        *(u64*)(fb + 192) = F3;
        __syncwarp();
    }
}

// ============================================================
// K3: coupling + edge-sum. warp = node, lane = channel pair, compacted ranks.
// ============================================================
#define KC_WARPS 4
__global__ void __launch_bounds__(128) k_coup() {
    __shared__ float4 s_u[KC_WARPS * 32];
    int t = threadIdx.x, w = t >> 5, lane = t & 31;
    int node = blockIdx.x * KC_WARPS + w;
    s_u[w * 32 + lane] = g_u[node * MM + lane];
    int nact = g_nact[node];
    __syncwarp();

    int c0 = lane * 2;
    float S0a = 0, S0b = 0, S1a = 0, S1b = 0;
    float U0a = 0, U0b = 0, U1a = 0, U1b = 0, U2a = 0, U2b = 0;
    float P0a = 0, P0b = 0, P1a = 0, P1b = 0, P2a = 0, P2b = 0;
    float Q0a = 0, Q0b = 0, Q1a = 0, Q1b = 0, Q2a = 0, Q2b = 0;

    for (int r = 0; r < nact; r += 2) {
        bool two = (r + 1) < nact;
        float4 u0 = s_u[w * 32 + r];
        float4 u1 = s_u[w * 32 + ((r + 1) & 31)];
        int j0 = __float_as_int(u0.w), j1 = __float_as_int(u1.w);
        const float* p0 = g_pre + j0 * 256 + c0;
        const float* p1 = g_pre + j1 * 256 + c0;
        float2 A00 = *(const float2*)(p0);
        float2 A0y = *(const float2*)(p0 + 64);
        float2 A0z = *(const float2*)(p0 + 128);
        float2 A0x = *(const float2*)(p0 + 192);
        float2 B00 = *(const float2*)(p1);
        float2 B0y = *(const float2*)(p1 + 64);
        float2 B0z = *(const float2*)(p1 + 128);
        float2 B0x = *(const float2*)(p1 + 192);
        float2 F0 = *(const float2*)(g_fr + (node * MM + r) * 64 + c0);
        float2 F1 = *(const float2*)(g_fr + (node * MM + ((r + 1) & 31)) * 64 + c0);
        if (!two) { F1.x = 0.f; F1.y = 0.f; }
        {
            float uy = u0.x, uz = u0.y, ux = u0.z, fa = F0.x, fb = F0.y;
            float sa = A0y.x * uy + A0z.x * uz + A0x.x * ux;
            float sb = A0y.y * uy + A0z.y * uz + A0x.y * ux;
            float t0a = A00.x * fa, t0b = A00.y * fb;
            S0a += t0a;        S0b += t0b;
            S1a += sa * fa;    S1b += sb * fb;
            U0a += uy * t0a;   U0b += uy * t0b;
            U1a += uz * t0a;   U1b += uz * t0b;
            U2a += ux * t0a;   U2b += ux * t0b;
            P0a += A0y.x * fa; P0b += A0y.y * fb;
            P1a += A0z.x * fa; P1b += A0z.y * fb;
            P2a += A0x.x * fa; P2b += A0x.y * fb;
            float cya = A0z.x * ux - A0x.x * uz, cyb = A0z.y * ux - A0x.y * uz;
            float cza = A0x.x * uy - A0y.x * ux, czb = A0x.y * uy - A0y.y * ux;
            float cxa = A0y.x * uz - A0z.x * uy, cxb = A0y.y * uz - A0z.y * uy;
            Q0a += cya * fa;   Q0b += cyb * fb;
            Q1a += cza * fa;   Q1b += czb * fb;
            Q2a += cxa * fa;   Q2b += cxb * fb;
        }
        {
            float uy = u1.x, uz = u1.y, ux = u1.z, fa = F1.x, fb = F1.y;
            float sa = B0y.x * uy + B0z.x * uz + B0x.x * ux;
            float sb = B0y.y * uy + B0z.y * uz + B0x.y * ux;
            float t0a = B00.x * fa, t0b = B00.y * fb;
            S0a += t0a;        S0b += t0b;
            S1a += sa * fa;    S1b += sb * fb;
            U0a += uy * t0a;   U0b += uy * t0b;
            U1a += uz * t0a;   U1b += uz * t0b;
            U2a += ux * t0a;   U2b += ux * t0b;
            P0a += B0y.x * fa; P0b += B0y.y * fb;
            P1a += B0z.x * fa; P1b += B0z.y * fb;
            P2a += B0x.x * fa; P2b += B0x.y * fb;
            float cya = B0z.x * ux - B0x.x * uz, cyb = B0z.y * ux - B0x.y * uz;
            float cza = B0x.x * uy - B0y.x * ux, czb = B0x.y * uy - B0y.y * ux;
            float cxa = B0y.x * uz - B0z.x * uy, cxb = B0y.y * uz - B0z.y * uy;
            Q0a += cya * fa;   Q0b += cyb * fb;
            Q1a += cza * fa;   Q1b += czb * fb;
            Q2a += cxa * fa;   Q2b += cxb * fb;
        }
    }

    float* dst = g_acc + node * 704 + c0;
    *(float2*)(dst + 0)   = make_float2(S0a, S0b);
    *(float2*)(dst + 64)  = make_float2(S1a, S1b);
    *(float2*)(dst + 128) = make_float2(U0a, U0b);
    *(float2*)(dst + 192) = make_float2(U1a, U1b);
    *(float2*)(dst + 256) = make_float2(U2a, U2b);
    *(float2*)(dst + 320) = make_float2(P0a, P0b);
    *(float2*)(dst + 384) = make_float2(P1a, P1b);
    *(float2*)(dst + 448) = make_float2(P2a, P2b);
    *(float2*)(dst + 512) = make_float2(Q0a, Q0b);
    *(float2*)(dst + 576) = make_float2(Q1a, Q1b);
    *(float2*)(dst + 640) = make_float2(Q2a, Q2b);
}

// ============================================================
// K4: hoisted w_a GEMM.  8 nodes/block, thread = (node, 4 g-rows, 2 cols).
// ============================================================
#define KAG_SMEM ((8192 + 12288 + 192 * 36) * 4)
__global__ void __launch_bounds__(256) k_ag(const float* __restrict__ wa0,
                                            const float* __restrict__ wa1) {
    extern __shared__ float sm[];
    float* sW0 = sm;             // wa0 [128][64]
    float* sW1 = sm + 8192;      // wa1 [192][64]
    float* sAt = sm + 20480;     // [k192][row32], stride 36
    int t = threadIdx.x;
    for (int i = t; i < 2048; i += 256) ((float4*)sW0)[i] = ((const float4*)wa0)[i];
    for (int i = t; i < 3072; i += 256) ((float4*)sW1)[i] = ((const float4*)wa1)[i];
    int nodeBase = blockIdx.x * 8;
    for (int f = t; f < 1408; f += 256) {
        int nl = f / 176, off4 = f % 176;
        float4 v = *((const float4*)(g_acc + (nodeBase + nl) * 704) + off4);
        int off = off4 * 4;
        int k, g;
        if (off < 128) { k = off; g = 0; }
        else {
            int q = off - 128;
            int seg = q / 192, rem = q % 192;
            g = rem / 64 + 1;
            k = seg * 64 + (rem & 63);
        }
        int row = nl * 4 + g;
        sAt[(k + 0) * 36 + row] = v.x;
        sAt[(k + 1) * 36 + row] = v.y;
        sAt[(k + 2) * 36 + row] = v.z;
        sAt[(k + 3) * 36 + row] = v.w;
    }
    __syncthreads();
    int nl = t >> 5, c0 = (t & 31) * 2;
    u64 A0 = pk2(0.f, 0.f), A1 = A0, A2 = A0, A3 = A0;
#pragma unroll 4
    for (int k = 0; k < 128; k++) {
        float4 a = *(const float4*)(sAt + k * 36 + nl * 4);
        u64 w0 = *(const u64*)(sW0 + k * 64 + c0);
        u64 w1 = *(const u64*)(sW1 + k * 64 + c0);
        A0 = fma2_(pk2(a.x, a.x), w0, A0);
        A1 = fma2_(pk2(a.y, a.y), w1, A1);
        A2 = fma2_(pk2(a.z, a.z), w1, A2);
        A3 = fma2_(pk2(a.w, a.w), w1, A3);
    }
#pragma unroll 4
    for (int k = 128; k < 192; k++) {
        float4 a = *(const float4*)(sAt + k * 36 + nl * 4);
        u64 w1 = *(const u64*)(sW1 + k * 64 + c0);
        A1 = fma2_(pk2(a.y, a.y), w1, A1);
        A2 = fma2_(pk2(a.z, a.z), w1, A2);
        A3 = fma2_(pk2(a.w, a.w), w1, A3);
    }
    float* dst = g_agg + (nodeBase + nl) * 256 + c0;
    *(u64*)(dst) = A0;
    *(u64*)(dst + 64) = A1;
    *(u64*)(dst + 128) = A2;
    *(u64*)(dst + 192) = A3;
}

// ============================================================
// K5: gate + w_b ielin + residual. 16 nodes/block, GEMM like k_pre.
// ============================================================
#define KFN_SMEM ((8192 + 4096 + 64 * 68) * 4)
__global__ void __launch_bounds__(256) k_fin(const float* __restrict__ feat,
                                             const float* __restrict__ wb0,
                                             const float* __restrict__ wb1,
                                             float* __restrict__ out) {
    extern __shared__ float sm[];
    float* sW0 = sm;
    float* sW1 = sm + 4096;
    float* sAg = sm + 8192;   // raw agg 16x256
    float* sAt = sm + 12288;  // gated transposed [k][row], stride 68
    int t = threadIdx.x;
    for (int i = t; i < 1024; i += 256) ((float4*)sW0)[i] = ((const float4*)wb0)[i];
    for (int i = t; i < 1024; i += 256) ((float4*)sW1)[i] = ((const float4*)wb1)[i];
    int nodeBase = blockIdx.x * 16;
    for (int i = t; i < 1024; i += 256)
        ((float4*)sAg)[i] = *((const float4*)(g_agg + nodeBase * 256) + i);
    __syncthreads();
    for (int i = t; i < 1024; i += 256) {
        int nl = i >> 6, c = i & 63;
        const float* a = sAg + nl * 256;
        float a0 = a[c], v1 = a[64 + c], v2 = a[128 + c], v3 = a[192 + c];
        float gt0 = ssp(a0);
        float gt1 = ssp(sqrtf(v1 * v1 + v2 * v2 + v3 * v3 + 1e-12f));
        int row = nl * 4;
        sAt[c * 68 + row] = a0 * gt0;
        sAt[c * 68 + row + 1] = v1 * gt1;
        sAt[c * 68 + row + 2] = v2 * gt1;
        sAt[c * 68 + row + 3] = v3 * gt1;
    }
    __syncthreads();
    int rg = t >> 5, c0 = (t & 31) * 2;
    u64 acc[8];
#pragma unroll
    for (int j = 0; j < 8; j++) acc[j] = pk2(0.f, 0.f);
#pragma unroll 4
    for (int k = 0; k < 64; k++) {
        float4 a0 = *(const float4*)(sAt + k * 68 + rg * 8);
        float4 a1 = *(const float4*)(sAt + k * 68 + rg * 8 + 4);
        u64 w0 = *(const u64*)(sW0 + k * 64 + c0);
        u64 w1 = *(const u64*)(sW1 + k * 64 + c0);
        acc[0] = fma2_(pk2(a0.x, a0.x), w0, acc[0]);
        acc[1] = fma2_(pk2(a0.y, a0.y), w1, acc[1]);
        acc[2] = fma2_(pk2(a0.z, a0.z), w1, acc[2]);
        acc[3] = fma2_(pk2(a0.w, a0.w), w1, acc[3]);
        acc[4] = fma2_(pk2(a1.x, a1.x), w0, acc[4]);
        acc[5] = fma2_(pk2(a1.y, a1.y), w1, acc[5]);
        acc[6] = fma2_(pk2(a1.z, a1.z), w1, acc[6]);
        acc[7] = fma2_(pk2(a1.w, a1.w), w1, acc[7]);
    }
#pragma unroll
    for (int j = 0; j < 8; j++) {
        int r = rg * 8 + j;
        int idx = nodeBase * 256 + r * 64 + c0;
        float2 fv = *(const float2*)(feat + idx);
        float oa, ob;
        upk2(acc[j], oa, ob);
        *(float2*)(out + idx) = make_float2(fv.x + oa, fv.y + ob);
    }
}

// ============================================================
extern "C" void kernel_launch(void* const* d_in, const int* in_sizes, int n_in,
                              void* d_out, int out_size) {
    const float* xyz = (const float*)d_in[0];
    const float* feat = (const float*)d_in[1];
    const float* wf1 = (const float*)d_in[2];
    const float* wf2 = (const float*)d_in[3];
    const float* wp0 = (const float*)d_in[4];
    const float* wp1 = (const float*)d_in[5];
    const float* wa0 = (const float*)d_in[6];
    const float* wa1 = (const float*)d_in[7];
    const float* wb0 = (const float*)d_in[8];
    const float* wb1 = (const float*)d_in[9];
    const int* src = (const int*)d_in[10];
    const int* emask = (const int*)d_in[11];
    float* out = (float*)d_out;

    cudaFuncSetAttribute(k_pre, cudaFuncAttributeMaxDynamicSharedMemorySize, KP_SMEM);
    cudaFuncSetAttribute(k_filt, cudaFuncAttributeMaxDynamicSharedMemorySize, KF_SMEM);
    cudaFuncSetAttribute(k_ag, cudaFuncAttributeMaxDynamicSharedMemorySize, KAG_SMEM);
    cudaFuncSetAttribute(k_fin, cudaFuncAttributeMaxDynamicSharedMemorySize, KFN_SMEM);

    k_pre<<<256, 256, KP_SMEM>>>(feat, wp0, wp1);
    k_filt<<<NN / KF_WARPS, 128, KF_SMEM>>>(xyz, wf1, wf2, src, emask);
    k_coup<<<NN / KC_WARPS, 128>>>();
    k_ag<<<512, 256, KAG_SMEM>>>(wa0, wa1);
    k_fin<<<256, 256, KFN_SMEM>>>(feat, wb0, wb1, out);
}

// round 4
// speedup vs baseline: 2.5125x; 1.1563x over previous
#include <cuda_runtime.h>

#define NN 4096
#define MM 32
#define LOG2F_ 0.693147180559945f

typedef unsigned long long u64;

// ---- scratch globals ----
__device__ float g_pre[NN * 256];     // ielin(feat) per node
__device__ float g_fr[NN * MM * 64];  // radial filters, rank-compacted per node
__device__ float4 g_u[NN * MM];       // (uy,uz,ux, j-as-float), rank-compacted
__device__ int g_nact[NN];            // active edge count per node
__device__ float g_acc[NN * 704];     // coupling accumulators
__device__ float g_agg[NN * 256];     // post-w_a aggregate

__device__ __forceinline__ float ssp(float x) {
    return fmaxf(x, 0.f) + __logf(1.f + __expf(-fabsf(x))) - LOG2F_;
}
__device__ __forceinline__ u64 pk2(float a, float b) {
    u64 r; asm("mov.b64 %0, {%1, %2};" : "=l"(r) : "f"(a), "f"(b)); return r;
}
__device__ __forceinline__ void upk2(u64 v, float& a, float& b) {
    asm("mov.b64 {%0, %1}, %2;" : "=f"(a), "=f"(b) : "l"(v));
}
__device__ __forceinline__ u64 fma2_(u64 a, u64 b, u64 c) {
    u64 r; asm("fma.rn.f32x2 %0, %1, %2, %3;" : "=l"(r) : "l"(a), "l"(b), "l"(c)); return r;
}

// ============================================================
// K1: g_pre = ielin(feat, wp0, wp1).  64 rows/block (16 nodes x 4 groups).
// ============================================================
#define KP_SMEM ((8192 + 64 * 68) * 4)
__global__ void __launch_bounds__(256) k_pre(const float* __restrict__ feat,
                                             const float* __restrict__ wp0,
                                             const float* __restrict__ wp1) {
    extern __shared__ float sm[];
    float* sW0 = sm;
    float* sW1 = sm + 4096;
    float* sAt = sm + 8192;  // [k][row], stride 68
    int t = threadIdx.x;
    for (int i = t; i < 1024; i += 256) ((float4*)sW0)[i] = ((const float4*)wp0)[i];
    for (int i = t; i < 1024; i += 256) ((float4*)sW1)[i] = ((const float4*)wp1)[i];
    const float4* src = (const float4*)feat + blockIdx.x * 1024;
#pragma unroll
    for (int jj = 0; jj < 4; jj++) {
        int idx = t + jj * 256;
        float4 v = src[idx];
        int d = idx * 4, r = d >> 6, k0 = d & 63;
        sAt[(k0 + 0) * 68 + r] = v.x;
        sAt[(k0 + 1) * 68 + r] = v.y;
        sAt[(k0 + 2) * 68 + r] = v.z;
        sAt[(k0 + 3) * 68 + r] = v.w;
    }
    __syncthreads();
    int rg = t >> 5, c0 = (t & 31) * 2;
    u64 acc[8];
#pragma unroll
    for (int j = 0; j < 8; j++) acc[j] = pk2(0.f, 0.f);
#pragma unroll 4
    for (int k = 0; k < 64; k++) {
        float4 a0 = *(const float4*)(sAt + k * 68 + rg * 8);
        float4 a1 = *(const float4*)(sAt + k * 68 + rg * 8 + 4);
        u64 w0 = *(const u64*)(sW0 + k * 64 + c0);
        u64 w1 = *(const u64*)(sW1 + k * 64 + c0);
        acc[0] = fma2_(pk2(a0.x, a0.x), w0, acc[0]);
        acc[1] = fma2_(pk2(a0.y, a0.y), w1, acc[1]);
        acc[2] = fma2_(pk2(a0.z, a0.z), w1, acc[2]);
        acc[3] = fma2_(pk2(a0.w, a0.w), w1, acc[3]);
        acc[4] = fma2_(pk2(a1.x, a1.x), w0, acc[4]);
        acc[5] = fma2_(pk2(a1.y, a1.y), w1, acc[5]);
        acc[6] = fma2_(pk2(a1.z, a1.z), w1, acc[6]);
        acc[7] = fma2_(pk2(a1.w, a1.w), w1, acc[7]);
    }
#pragma unroll
    for (int j = 0; j < 8; j++) {
        int r = rg * 8 + j;
        *(u64*)(g_pre + blockIdx.x * 4096 + r * 64 + c0) = acc[j];
    }
}

// ============================================================
// K2: radial filters. 8 warps/block, warp = node, 8-edge tiles.
// ============================================================
#define KF_WARPS 8
#define KF_PW (16 * 36 + 8 * 68)   // sRB + sH = 576 + 544 = 1120 floats/warp
#define KF_SMEM ((1024 + 4096 + KF_WARPS * KF_PW) * 4)
__global__ void __launch_bounds__(256, 3) k_filt(const float* __restrict__ xyz,
                                                 const float* __restrict__ wf1,
                                                 const float* __restrict__ wf2,
                                                 const int* __restrict__ src,
                                                 const int* __restrict__ emask) {
    extern __shared__ float sm[];
    float* sW1 = sm;        // wf1 [16][64]
    float* sW2 = sm + 1024; // wf2 [64][64]
    int t = threadIdx.x, w = t >> 5, lane = t & 31;
    for (int i = t; i < 256; i += 256) ((float4*)sW1)[i] = ((const float4*)wf1)[i];
    for (int i = t; i < 1024; i += 256) ((float4*)sW2)[i] = ((const float4*)wf2)[i];
    float* sRB = sm + 5120 + w * KF_PW;  // [q16][36] rank-compacted
    float* sH = sRB + 576;               // [e8][68]
    __syncthreads();

    int node = blockIdx.x * KF_WARPS + w;
    // ---- phase A: lane = edge ----
    int eid = node * MM + lane;
    int mk = emask[eid];
    int j = src[eid];
    float nx = xyz[node * 3], ny = xyz[node * 3 + 1], nz = xyz[node * 3 + 2];
    float rx = xyz[j * 3] - nx, ry = xyz[j * 3 + 1] - ny, rz = xyz[j * 3 + 2] - nz;
    float d2 = rx * rx + ry * ry + rz * rz;
    float invd = rsqrtf(d2);
    float x = d2 * invd * 0.2f;
    bool act = (mk != 0) && (x < 1.f);
    unsigned actmask = __ballot_sync(0xffffffffu, act);
    int nact = __popc(actmask);
    int rank = __popc(actmask & ((1u << lane) - 1u));
    if (lane == 0) g_nact[node] = nact;
    if (act) {
        float x3 = x * x * x;
        float env = 1.f + x3 * (-10.f + x * (15.f - 6.f * x));
        float scale = env * invd;
        g_u[node * MM + rank] = make_float4(ry * invd, rz * invd, rx * invd, __int_as_float(j));
#pragma unroll
        for (int q = 0; q < 16; q++) sRB[q * 36 + rank] = __sinf(x * (float)q) * scale;
    }
    __syncwarp();

    // ---- phase B: 8-edge tiles; lane = channel pair k0 ----
    int k0 = lane * 2;
    for (int r0 = 0; r0 < nact; r0 += 8) {
        // h GEMM: (16 -> 64) for 8 edges
        u64 H0 = pk2(0.f, 0.f), H1 = H0, H2 = H0, H3 = H0, H4 = H0, H5 = H0, H6 = H0, H7 = H0;
#pragma unroll
        for (int q = 0; q < 16; q++) {
            float4 ra = *(const float4*)(sRB + q * 36 + r0);
            float4 rb = *(const float4*)(sRB + q * 36 + r0 + 4);
            u64 wv = *(const u64*)(sW1 + q * 64 + k0);
            H0 = fma2_(pk2(ra.x, ra.x), wv, H0);
            H1 = fma2_(pk2(ra.y, ra.y), wv, H1);
            H2 = fma2_(pk2(ra.z, ra.z), wv, H2);
            H3 = fma2_(pk2(ra.w, ra.w), wv, H3);
            H4 = fma2_(pk2(rb.x, rb.x), wv, H4);
            H5 = fma2_(pk2(rb.y, rb.y), wv, H5);
            H6 = fma2_(pk2(rb.z, rb.z), wv, H6);
            H7 = fma2_(pk2(rb.w, rb.w), wv, H7);
        }
        {
            float a, b;
            upk2(H0, a, b); *(u64*)(sH + 0 * 68 + k0) = pk2(ssp(a), ssp(b));
            upk2(H1, a, b); *(u64*)(sH + 1 * 68 + k0) = pk2(ssp(a), ssp(b));
            upk2(H2, a, b); *(u64*)(sH + 2 * 68 + k0) = pk2(ssp(a), ssp(b));
            upk2(H3, a, b); *(u64*)(sH + 3 * 68 + k0) = pk2(ssp(a), ssp(b));
            upk2(H4, a, b); *(u64*)(sH + 4 * 68 + k0) = pk2(ssp(a), ssp(b));
            upk2(H5, a, b); *(u64*)(sH + 5 * 68 + k0) = pk2(ssp(a), ssp(b));
            upk2(H6, a, b); *(u64*)(sH + 6 * 68 + k0) = pk2(ssp(a), ssp(b));
            upk2(H7, a, b); *(u64*)(sH + 7 * 68 + k0) = pk2(ssp(a), ssp(b));
        }
        __syncwarp();
        // fr GEMM: (64 -> 64) for 8 edges
        u64 F0 = pk2(0.f, 0.f), F1 = F0, F2 = F0, F3 = F0, F4 = F0, F5 = F0, F6 = F0, F7 = F0;
#pragma unroll 2
        for (int kk = 0; kk < 64; kk += 4) {
            float4 h0 = *(const float4*)(sH + 0 * 68 + kk);
            float4 h1 = *(const float4*)(sH + 1 * 68 + kk);
            float4 h2 = *(const float4*)(sH + 2 * 68 + kk);
            float4 h3 = *(const float4*)(sH + 3 * 68 + kk);
            float4 h4 = *(const float4*)(sH + 4 * 68 + kk);
            float4 h5 = *(const float4*)(sH + 5 * 68 + kk);
            float4 h6 = *(const float4*)(sH + 6 * 68 + kk);
            float4 h7 = *(const float4*)(sH + 7 * 68 + kk);
            u64 w0 = *(const u64*)(sW2 + (kk + 0) * 64 + k0);
            u64 w1 = *(const u64*)(sW2 + (kk + 1) * 64 + k0);
            u64 w2 = *(const u64*)(sW2 + (kk + 2) * 64 + k0);
            u64 w3 = *(const u64*)(sW2 + (kk + 3) * 64 + k0);
#define FRS(CM, WV) \
            F0 = fma2_(pk2(h0.CM, h0.CM), WV, F0); \
            F1 = fma2_(pk2(h1.CM, h1.CM), WV, F1); \
            F2 = fma2_(pk2(h2.CM, h2.CM), WV, F2); \
            F3 = fma2_(pk2(h3.CM, h3.CM), WV, F3); \
            F4 = fma2_(pk2(h4.CM, h4.CM), WV, F4); \
            F5 = fma2_(pk2(h5.CM, h5.CM), WV, F5); \
            F6 = fma2_(pk2(h6.CM, h6.CM), WV, F6); \
            F7 = fma2_(pk2(h7.CM, h7.CM), WV, F7);
            FRS(x, w0) FRS(y, w1) FRS(z, w2) FRS(w, w3)
#undef FRS
        }
        float* fb = g_fr + (node * MM + r0) * 64 + k0;
        *(u64*)(fb + 0 * 64) = F0;
        *(u64*)(fb + 1 * 64) = F1;
        *(u64*)(fb + 2 * 64) = F2;
        *(u64*)(fb + 3 * 64) = F3;
        *(u64*)(fb + 4 * 64) = F4;
        *(u64*)(fb + 5 * 64) = F5;
        *(u64*)(fb + 6 * 64) = F6;
        *(u64*)(fb + 7 * 64) = F7;
        __syncwarp();
    }
}

// ============================================================
// K3: coupling + edge-sum. warp = node, lane = channel pair, compacted ranks.
// ============================================================
#define KC_WARPS 8
__global__ void __launch_bounds__(256) k_coup() {
    __shared__ float4 s_u[KC_WARPS * 32];
    int t = threadIdx.x, w = t >> 5, lane = t & 31;
    int node = blockIdx.x * KC_WARPS + w;
    s_u[w * 32 + lane] = g_u[node * MM + lane];
    int nact = g_nact[node];
    __syncwarp();

    int c0 = lane * 2;
    float S0a = 0, S0b = 0, S1a = 0, S1b = 0;
    float U0a = 0, U0b = 0, U1a = 0, U1b = 0, U2a = 0, U2b = 0;
    float P0a = 0, P0b = 0, P1a = 0, P1b = 0, P2a = 0, P2b = 0;
    float Q0a = 0, Q0b = 0, Q1a = 0, Q1b = 0, Q2a = 0, Q2b = 0;

    for (int r = 0; r < nact; r += 2) {
        bool two = (r + 1) < nact;
        float4 u0 = s_u[w * 32 + r];
        float4 u1 = s_u[w * 32 + ((r + 1) & 31)];
        int j0 = __float_as_int(u0.w), j1 = __float_as_int(u1.w);
        const float* p0 = g_pre + j0 * 256 + c0;
        const float* p1 = g_pre + j1 * 256 + c0;
        float2 A00 = *(const float2*)(p0);
        float2 A0y = *(const float2*)(p0 + 64);
        float2 A0z = *(const float2*)(p0 + 128);
        float2 A0x = *(const float2*)(p0 + 192);
        float2 B00 = *(const float2*)(p1);
        float2 B0y = *(const float2*)(p1 + 64);
        float2 B0z = *(const float2*)(p1 + 128);
        float2 B0x = *(const float2*)(p1 + 192);
        float2 F0 = *(const float2*)(g_fr + (node * MM + r) * 64 + c0);
        float2 F1 = *(const float2*)(g_fr + (node * MM + ((r + 1) & 31)) * 64 + c0);
        if (!two) { F1.x = 0.f; F1.y = 0.f; }
        {
            float uy = u0.x, uz = u0.y, ux = u0.z, fa = F0.x, fb = F0.y;
            float sa = A0y.x * uy + A0z.x * uz + A0x.x * ux;
            float sb = A0y.y * uy + A0z.y * uz + A0x.y * ux;
            float t0a = A00.x * fa, t0b = A00.y * fb;
            S0a += t0a;        S0b += t0b;
            S1a += sa * fa;    S1b += sb * fb;
            U0a += uy * t0a;   U0b += uy * t0b;
            U1a += uz * t0a;   U1b += uz * t0b;
            U2a += ux * t0a;   U2b += ux * t0b;
            P0a += A0y.x * fa; P0b += A0y.y * fb;
            P1a += A0z.x * fa; P1b += A0z.y * fb;
            P2a += A0x.x * fa; P2b += A0x.y * fb;
            float cya = A0z.x * ux - A0x.x * uz, cyb = A0z.y * ux - A0x.y * uz;
            float cza = A0x.x * uy - A0y.x * ux, czb = A0x.y * uy - A0y.y * ux;
            float cxa = A0y.x * uz - A0z.x * uy, cxb = A0y.y * uz - A0z.y * uy;
            Q0a += cya * fa;   Q0b += cyb * fb;
            Q1a += cza * fa;   Q1b += czb * fb;
            Q2a += cxa * fa;   Q2b += cxb * fb;
        }
        {
            float uy = u1.x, uz = u1.y, ux = u1.z, fa = F1.x, fb = F1.y;
            float sa = B0y.x * uy + B0z.x * uz + B0x.x * ux;
            float sb = B0y.y * uy + B0z.y * uz + B0x.y * ux;
            float t0a = B00.x * fa, t0b = B00.y * fb;
            S0a += t0a;        S0b += t0b;
            S1a += sa * fa;    S1b += sb * fb;
            U0a += uy * t0a;   U0b += uy * t0b;
            U1a += uz * t0a;   U1b += uz * t0b;
            U2a += ux * t0a;   U2b += ux * t0b;
            P0a += B0y.x * fa; P0b += B0y.y * fb;
            P1a += B0z.x * fa; P1b += B0z.y * fb;
            P2a += B0x.x * fa; P2b += B0x.y * fb;
            float cya = B0z.x * ux - B0x.x * uz, cyb = B0z.y * ux - B0x.y * uz;
            float cza = B0x.x * uy - B0y.x * ux, czb = B0x.y * uy - B0y.y * ux;
            float cxa = B0y.x * uz - B0z.x * uy, cxb = B0y.y * uz - B0z.y * uy;
            Q0a += cya * fa;   Q0b += cyb * fb;
            Q1a += cza * fa;   Q1b += czb * fb;
            Q2a += cxa * fa;   Q2b += cxb * fb;
        }
    }

    float* dst = g_acc + node * 704 + c0;
    *(float2*)(dst + 0)   = make_float2(S0a, S0b);
    *(float2*)(dst + 64)  = make_float2(S1a, S1b);
    *(float2*)(dst + 128) = make_float2(U0a, U0b);
    *(float2*)(dst + 192) = make_float2(U1a, U1b);
    *(float2*)(dst + 256) = make_float2(U2a, U2b);
    *(float2*)(dst + 320) = make_float2(P0a, P0b);
    *(float2*)(dst + 384) = make_float2(P1a, P1b);
    *(float2*)(dst + 448) = make_float2(P2a, P2b);
    *(float2*)(dst + 512) = make_float2(Q0a, Q0b);
    *(float2*)(dst + 576) = make_float2(Q1a, Q1b);
    *(float2*)(dst + 640) = make_float2(Q2a, Q2b);
}

// ============================================================
// K4a: l0 aggregate GEMM (4096x128)@(128x64). A read via LDG (block-private).
//   16 nodes/block, warp = 2 rows, lane = 2 cols. 256 blocks.
// ============================================================
__global__ void __launch_bounds__(256) k_ag0(const float* __restrict__ wa0) {
    __shared__ float sW[8192];
    int t = threadIdx.x;
    for (int i = t; i < 2048; i += 256) ((float4*)sW)[i] = ((const float4*)wa0)[i];
    __syncthreads();
    int w = t >> 5, lane = t & 31, c0 = lane * 2;
    int n0 = blockIdx.x * 16 + w * 2;
    const float* A0 = g_acc + n0 * 704;
    const float* A1 = A0 + 704;
    u64 acc0 = pk2(0.f, 0.f), acc1 = acc0;
#pragma unroll 4
    for (int kk = 0; kk < 128; kk += 4) {
        float4 a0 = *(const float4*)(A0 + kk);
        float4 a1 = *(const float4*)(A1 + kk);
        u64 w0 = *(const u64*)(sW + (kk + 0) * 64 + c0);
        u64 w1 = *(const u64*)(sW + (kk + 1) * 64 + c0);
        u64 w2 = *(const u64*)(sW + (kk + 2) * 64 + c0);
        u64 w3 = *(const u64*)(sW + (kk + 3) * 64 + c0);
        acc0 = fma2_(pk2(a0.x, a0.x), w0, acc0);
        acc1 = fma2_(pk2(a1.x, a1.x), w0, acc1);
        acc0 = fma2_(pk2(a0.y, a0.y), w1, acc0);
        acc1 = fma2_(pk2(a1.y, a1.y), w1, acc1);
        acc0 = fma2_(pk2(a0.z, a0.z), w2, acc0);
        acc1 = fma2_(pk2(a1.z, a1.z), w2, acc1);
        acc0 = fma2_(pk2(a0.w, a0.w), w3, acc0);
        acc1 = fma2_(pk2(a1.w, a1.w), w3, acc1);
    }
    *(u64*)(g_agg + n0 * 256 + c0) = acc0;
    *(u64*)(g_agg + (n0 + 1) * 256 + c0) = acc1;
}

// ============================================================
// K4b: l1 aggregate GEMM (12288x192)@(192x64). Rows = (node,m).
//   32 rows/block, thread = 4 rows x 2 cols. 384 blocks. A via LDG.
// ============================================================
__global__ void __launch_bounds__(256) k_ag1(const float* __restrict__ wa1) {
    __shared__ float sW[12288];
    int t = threadIdx.x;
    for (int i = t; i < 3072; i += 256) ((float4*)sW)[i] = ((const float4*)wa1)[i];
    __syncthreads();
    int rg = t >> 5, c0 = (t & 31) * 2;
    int gr = blockIdx.x * 32 + rg * 4;
    int n_[4], m_[4];
#pragma unroll
    for (int jj = 0; jj < 4; jj++) {
        int g = gr + jj;
        n_[jj] = g / 3;
        m_[jj] = g - n_[jj] * 3;
    }
    u64 acc0 = pk2(0.f, 0.f), acc1 = acc0, acc2 = acc0, acc3 = acc0;
#pragma unroll
    for (int s = 0; s < 3; s++) {
        const float* p0 = g_acc + n_[0] * 704 + 128 + s * 192 + m_[0] * 64;
        const float* p1 = g_acc + n_[1] * 704 + 128 + s * 192 + m_[1] * 64;
        const float* p2 = g_acc + n_[2] * 704 + 128 + s * 192 + m_[2] * 64;
        const float* p3 = g_acc + n_[3] * 704 + 128 + s * 192 + m_[3] * 64;
        const float* ws = sW + s * 64 * 64;
#pragma unroll 4
        for (int kk = 0; kk < 64; kk += 4) {
            float4 a0 = *(const float4*)(p0 + kk);
            float4 a1 = *(const float4*)(p1 + kk);
            float4 a2 = *(const float4*)(p2 + kk);
            float4 a3 = *(const float4*)(p3 + kk);
            u64 w0 = *(const u64*)(ws + (kk + 0) * 64 + c0);
            u64 w1 = *(const u64*)(ws + (kk + 1) * 64 + c0);
            u64 w2 = *(const u64*)(ws + (kk + 2) * 64 + c0);
            u64 w3 = *(const u64*)(ws + (kk + 3) * 64 + c0);
            acc0 = fma2_(pk2(a0.x, a0.x), w0, acc0);
            acc1 = fma2_(pk2(a1.x, a1.x), w0, acc1);
            acc2 = fma2_(pk2(a2.x, a2.x), w0, acc2);
            acc3 = fma2_(pk2(a3.x, a3.x), w0, acc3);
            acc0 = fma2_(pk2(a0.y, a0.y), w1, acc0);
            acc1 = fma2_(pk2(a1.y, a1.y), w1, acc1);
            acc2 = fma2_(pk2(a2.y, a2.y), w1, acc2);
            acc3 = fma2_(pk2(a3.y, a3.y), w1, acc3);
            acc0 = fma2_(pk2(a0.z, a0.z), w2, acc0);
            acc1 = fma2_(pk2(a1.z, a1.z), w2, acc1);
            acc2 = fma2_(pk2(a2.z, a2.z), w2, acc2);
            acc3 = fma2_(pk2(a3.z, a3.z), w2, acc3);
            acc0 = fma2_(pk2(a0.w, a0.w), w3, acc0);
            acc1 = fma2_(pk2(a1.w, a1.w), w3, acc1);
            acc2 = fma2_(pk2(a2.w, a2.w), w3, acc2);
            acc3 = fma2_(pk2(a3.w, a3.w), w3, acc3);
        }
    }
    *(u64*)(g_agg + n_[0] * 256 + (m_[0] + 1) * 64 + c0) = acc0;
    *(u64*)(g_agg + n_[1] * 256 + (m_[1] + 1) * 64 + c0) = acc1;
    *(u64*)(g_agg + n_[2] * 256 + (m_[2] + 1) * 64 + c0) = acc2;
    *(u64*)(g_agg + n_[3] * 256 + (m_[3] + 1) * 64 + c0) = acc3;
}

// ============================================================
// K5: gate + w_b ielin + residual. 16 nodes/block.
// ============================================================
#define KFN_SMEM ((8192 + 4096 + 64 * 68) * 4)
__global__ void __launch_bounds__(256) k_fin(const float* __restrict__ feat,
                                             const float* __restrict__ wb0,
                                             const float* __restrict__ wb1,
                                             float* __restrict__ out) {
    extern __shared__ float sm[];
    float* sW0 = sm;
    float* sW1 = sm + 4096;
    float* sAg = sm + 8192;   // raw agg 16x256
    float* sAt = sm + 12288;  // gated transposed [k][row], stride 68
    int t = threadIdx.x;
    for (int i = t; i < 1024; i += 256) ((float4*)sW0)[i] = ((const float4*)wb0)[i];
    for (int i = t; i < 1024; i += 256) ((float4*)sW1)[i] = ((const float4*)wb1)[i];
    int nodeBase = blockIdx.x * 16;
    for (int i = t; i < 1024; i += 256)
        ((float4*)sAg)[i] = *((const float4*)(g_agg + nodeBase * 256) + i);
    __syncthreads();
    for (int i = t; i < 1024; i += 256) {
        int nl = i >> 6, c = i & 63;
        const float* a = sAg + nl * 256;
        float a0 = a[c], v1 = a[64 + c], v2 = a[128 + c], v3 = a[192 + c];
        float gt0 = ssp(a0);
        float gt1 = ssp(sqrtf(v1 * v1 + v2 * v2 + v3 * v3 + 1e-12f));
        int row = nl * 4;
        sAt[c * 68 + row] = a0 * gt0;
        sAt[c * 68 + row + 1] = v1 * gt1;
        sAt[c * 68 + row + 2] = v2 * gt1;
        sAt[c * 68 + row + 3] = v3 * gt1;
    }
    __syncthreads();
    int rg = t >> 5, c0 = (t & 31) * 2;
    u64 acc[8];
#pragma unroll
    for (int j = 0; j < 8; j++) acc[j] = pk2(0.f, 0.f);
#pragma unroll 4
    for (int k = 0; k < 64; k++) {
        float4 a0 = *(const float4*)(sAt + k * 68 + rg * 8);
        float4 a1 = *(const float4*)(sAt + k * 68 + rg * 8 + 4);
        u64 w0 = *(const u64*)(sW0 + k * 64 + c0);
        u64 w1 = *(const u64*)(sW1 + k * 64 + c0);
        acc[0] = fma2_(pk2(a0.x, a0.x), w0, acc[0]);
        acc[1] = fma2_(pk2(a0.y, a0.y), w1, acc[1]);
        acc[2] = fma2_(pk2(a0.z, a0.z), w1, acc[2]);
        acc[3] = fma2_(pk2(a0.w, a0.w), w1, acc[3]);
        acc[4] = fma2_(pk2(a1.x, a1.x), w0, acc[4]);
        acc[5] = fma2_(pk2(a1.y, a1.y), w1, acc[5]);
        acc[6] = fma2_(pk2(a1.z, a1.z), w1, acc[6]);
        acc[7] = fma2_(pk2(a1.w, a1.w), w1, acc[7]);
    }
#pragma unroll
    for (int j = 0; j < 8; j++) {
        int r = rg * 8 + j;
        int idx = nodeBase * 256 + r * 64 + c0;
        float2 fv = *(const float2*)(feat + idx);
        float oa, ob;
        upk2(acc[j], oa, ob);
        *(float2*)(out + idx) = make_float2(fv.x + oa, fv.y + ob);
    }
}

// ============================================================
extern "C" void kernel_launch(void* const* d_in, const int* in_sizes, int n_in,
                              void* d_out, int out_size) {
    const float* xyz = (const float*)d_in[0];
    const float* feat = (const float*)d_in[1];
    const float* wf1 = (const float*)d_in[2];
    const float* wf2 = (const float*)d_in[3];
    const float* wp0 = (const float*)d_in[4];
    const float* wp1 = (const float*)d_in[5];
    const float* wa0 = (const float*)d_in[6];
    const float* wa1 = (const float*)d_in[7];
    const float* wb0 = (const float*)d_in[8];
    const float* wb1 = (const float*)d_in[9];
    const int* src = (const int*)d_in[10];
    const int* emask = (const int*)d_in[11];
    float* out = (float*)d_out;

    cudaFuncSetAttribute(k_pre, cudaFuncAttributeMaxDynamicSharedMemorySize, KP_SMEM);
    cudaFuncSetAttribute(k_filt, cudaFuncAttributeMaxDynamicSharedMemorySize, KF_SMEM);
    cudaFuncSetAttribute(k_fin, cudaFuncAttributeMaxDynamicSharedMemorySize, KFN_SMEM);

    k_pre<<<256, 256, KP_SMEM>>>(feat, wp0, wp1);
    k_filt<<<NN / KF_WARPS, 256, KF_SMEM>>>(xyz, wf1, wf2, src, emask);
    k_coup<<<NN / KC_WARPS, 256>>>();
    k_ag0<<<256, 256>>>(wa0);
    k_ag1<<<384, 256>>>(wa1);
    k_fin<<<256, 256, KFN_SMEM>>>(feat, wb0, wb1, out);
}

// round 5
// speedup vs baseline: 2.6452x; 1.0528x over previous
#include <cuda_runtime.h>

#define NN 4096
#define MM 32
#define LOG2F_ 0.693147180559945f

typedef unsigned long long u64;

// ---- scratch globals ----
__device__ float g_pre[NN * 256];  // ielin(feat) per node
__device__ float g_acc[NN * 704];  // coupling accumulators
__device__ float g_agg[NN * 256];  // post-w_a aggregate

__device__ __forceinline__ float ssp(float x) {
    return fmaxf(x, 0.f) + __logf(1.f + __expf(-fabsf(x))) - LOG2F_;
}
__device__ __forceinline__ u64 pk2(float a, float b) {
    u64 r; asm("mov.b64 %0, {%1, %2};" : "=l"(r) : "f"(a), "f"(b)); return r;
}
__device__ __forceinline__ void upk2(u64 v, float& a, float& b) {
    asm("mov.b64 {%0, %1}, %2;" : "=f"(a), "=f"(b) : "l"(v));
}
__device__ __forceinline__ u64 fma2_(u64 a, u64 b, u64 c) {
    u64 r; asm("fma.rn.f32x2 %0, %1, %2, %3;" : "=l"(r) : "l"(a), "l"(b), "l"(c)); return r;
}

// ============================================================
// K1: g_pre = ielin(feat, wp0, wp1). 8 nodes/block (32 rows), grid 512.
// ============================================================
#define KP_SMEM ((4096 + 4096 + 64 * 36) * 4)
__global__ void __launch_bounds__(256) k_pre(const float* __restrict__ feat,
                                             const float* __restrict__ wp0,
                                             const float* __restrict__ wp1) {
    extern __shared__ float sm[];
    float* sW0 = sm;
    float* sW1 = sm + 4096;
    float* sAt = sm + 8192;  // [k64][row32], stride 36
    int t = threadIdx.x;
    for (int i = t; i < 1024; i += 256) {
        ((float4*)sW0)[i] = ((const float4*)wp0)[i];
        ((float4*)sW1)[i] = ((const float4*)wp1)[i];
    }
    const float4* src = (const float4*)feat + blockIdx.x * 512;
#pragma unroll
    for (int jj = 0; jj < 2; jj++) {
        int idx = t + jj * 256;
        float4 v = src[idx];
        int d = idx * 4, r = d >> 6, k0 = d & 63;
        sAt[(k0 + 0) * 36 + r] = v.x;
        sAt[(k0 + 1) * 36 + r] = v.y;
        sAt[(k0 + 2) * 36 + r] = v.z;
        sAt[(k0 + 3) * 36 + r] = v.w;
    }
    __syncthreads();
    int rg = t >> 5, c0 = (t & 31) * 2;
    u64 acc0 = pk2(0.f, 0.f), acc1 = acc0, acc2 = acc0, acc3 = acc0;
#pragma unroll 4
    for (int k = 0; k < 64; k++) {
        float4 a = *(const float4*)(sAt + k * 36 + rg * 4);
        u64 w0 = *(const u64*)(sW0 + k * 64 + c0);
        u64 w1 = *(const u64*)(sW1 + k * 64 + c0);
        acc0 = fma2_(pk2(a.x, a.x), w0, acc0);
        acc1 = fma2_(pk2(a.y, a.y), w1, acc1);
        acc2 = fma2_(pk2(a.z, a.z), w1, acc2);
        acc3 = fma2_(pk2(a.w, a.w), w1, acc3);
    }
    int node = blockIdx.x * 8 + rg;
    *(u64*)(g_pre + node * 256 + c0) = acc0;
    *(u64*)(g_pre + node * 256 + 64 + c0) = acc1;
    *(u64*)(g_pre + node * 256 + 128 + c0) = acc2;
    *(u64*)(g_pre + node * 256 + 192 + c0) = acc3;
}

// ============================================================
// K2: fused edge kernel (filters + coupling). warp = node, 8 warps/block.
//   fr stays in registers: lane's filter channel pair == its coupling pair.
//   Neighbor g_pre rows prefetched before GEMMs -> L2 latency hidden.
// ============================================================
#define KE_WARPS 8
#define KE_PW (576 + 272 + 128)  // sRB[16][36] + sH[4][68] + s_u[32]f4
#define KE_SMEM ((1024 + 4096 + KE_WARPS * KE_PW) * 4)

#define COUPLE(UE, A0, AY, AZ, AX, F) do { \
    float fa, fb; upk2(F, fa, fb); \
    float uy = UE.x, uz = UE.y, ux = UE.z; \
    float sa = AY.x * uy + AZ.x * uz + AX.x * ux; \
    float sb = AY.y * uy + AZ.y * uz + AX.y * ux; \
    float t0a = A0.x * fa, t0b = A0.y * fb; \
    S0a += t0a;       S0b += t0b; \
    S1a += sa * fa;   S1b += sb * fb; \
    U0a += uy * t0a;  U0b += uy * t0b; \
    U1a += uz * t0a;  U1b += uz * t0b; \
    U2a += ux * t0a;  U2b += ux * t0b; \
    P0a += AY.x * fa; P0b += AY.y * fb; \
    P1a += AZ.x * fa; P1b += AZ.y * fb; \
    P2a += AX.x * fa; P2b += AX.y * fb; \
    float cya = AZ.x * ux - AX.x * uz, cyb = AZ.y * ux - AX.y * uz; \
    float cza = AX.x * uy - AY.x * ux, czb = AX.y * uy - AY.y * ux; \
    float cxa = AY.x * uz - AZ.x * uy, cxb = AY.y * uz - AZ.y * uy; \
    Q0a += cya * fa;  Q0b += cyb * fb; \
    Q1a += cza * fa;  Q1b += czb * fb; \
    Q2a += cxa * fa;  Q2b += cxb * fb; \
} while (0)

__global__ void __launch_bounds__(256) k_edge(const float* __restrict__ xyz,
                                              const float* __restrict__ wf1,
                                              const float* __restrict__ wf2,
                                              const int* __restrict__ src,
                                              const int* __restrict__ emask) {
    extern __shared__ float sm[];
    float* sW1 = sm;         // wf1 [16][64]
    float* sW2 = sm + 1024;  // wf2 [64][64]
    int t = threadIdx.x, w = t >> 5, lane = t & 31;
    for (int i = t; i < 256; i += 256) ((float4*)sW1)[i] = ((const float4*)wf1)[i];
    for (int i = t; i < 1024; i += 256) ((float4*)sW2)[i] = ((const float4*)wf2)[i];
    float* base = sm + 5120 + w * KE_PW;
    float* sRB = base;                  // [q16][36]
    float* sH = base + 576;             // [e4][68]
    float4* s_u = (float4*)(base + 848); // [32] (uy,uz,ux,j)
    __syncthreads();

    int node = blockIdx.x * KE_WARPS + w;
    // ---- phase A: lane = edge ----
    s_u[lane] = make_float4(0.f, 0.f, 0.f, __int_as_float(node));
    __syncwarp();
    int eid = node * MM + lane;
    int mk = emask[eid];
    int j = src[eid];
    float nx = xyz[node * 3], ny = xyz[node * 3 + 1], nz = xyz[node * 3 + 2];
    float rx = xyz[j * 3] - nx, ry = xyz[j * 3 + 1] - ny, rz = xyz[j * 3 + 2] - nz;
    float d2 = rx * rx + ry * ry + rz * rz;
    float invd = rsqrtf(d2);
    float x = d2 * invd * 0.2f;
    bool act = (mk != 0) && (x < 1.f);
    unsigned actmask = __ballot_sync(0xffffffffu, act);
    int nact = __popc(actmask);
    int rank = __popc(actmask & ((1u << lane) - 1u));
    if (act) {
        float x3 = x * x * x;
        float env = 1.f + x3 * (-10.f + x * (15.f - 6.f * x));
        float scale = env * invd;
        s_u[rank] = make_float4(ry * invd, rz * invd, rx * invd, __int_as_float(j));
#pragma unroll
        for (int q = 0; q < 16; q++) sRB[q * 36 + rank] = __sinf(x * (float)q) * scale;
    }
    __syncwarp();

    // ---- phase B: 4-edge tiles; lane = channel pair c0 ----
    int c0 = lane * 2;
    float S0a = 0, S0b = 0, S1a = 0, S1b = 0;
    float U0a = 0, U0b = 0, U1a = 0, U1b = 0, U2a = 0, U2b = 0;
    float P0a = 0, P0b = 0, P1a = 0, P1b = 0, P2a = 0, P2b = 0;
    float Q0a = 0, Q0b = 0, Q1a = 0, Q1b = 0, Q2a = 0, Q2b = 0;

    for (int r0 = 0; r0 < nact; r0 += 4) {
        float4 ue0 = s_u[r0], ue1 = s_u[r0 + 1], ue2 = s_u[r0 + 2], ue3 = s_u[r0 + 3];
        const float* p0 = g_pre + __float_as_int(ue0.w) * 256 + c0;
        const float* p1 = g_pre + __float_as_int(ue1.w) * 256 + c0;
        const float* p2 = g_pre + __float_as_int(ue2.w) * 256 + c0;
        const float* p3 = g_pre + __float_as_int(ue3.w) * 256 + c0;
        // prefetch neighbor pre rows (latency hidden by the two GEMMs below)
        float2 A00 = *(const float2*)(p0), A0y = *(const float2*)(p0 + 64),
               A0z = *(const float2*)(p0 + 128), A0x = *(const float2*)(p0 + 192);
        float2 B00 = *(const float2*)(p1), B0y = *(const float2*)(p1 + 64),
               B0z = *(const float2*)(p1 + 128), B0x = *(const float2*)(p1 + 192);
        float2 C00 = *(const float2*)(p2), C0y = *(const float2*)(p2 + 64),
               C0z = *(const float2*)(p2 + 128), C0x = *(const float2*)(p2 + 192);
        float2 D00 = *(const float2*)(p3), D0y = *(const float2*)(p3 + 64),
               D0z = *(const float2*)(p3 + 128), D0x = *(const float2*)(p3 + 192);

        // h GEMM (16 -> 64), lane owns h-channel pair c0
        u64 H0 = pk2(0.f, 0.f), H1 = H0, H2 = H0, H3 = H0;
#pragma unroll
        for (int q = 0; q < 16; q++) {
            float4 rb = *(const float4*)(sRB + q * 36 + r0);
            u64 wv = *(const u64*)(sW1 + q * 64 + c0);
            H0 = fma2_(pk2(rb.x, rb.x), wv, H0);
            H1 = fma2_(pk2(rb.y, rb.y), wv, H1);
            H2 = fma2_(pk2(rb.z, rb.z), wv, H2);
            H3 = fma2_(pk2(rb.w, rb.w), wv, H3);
        }
        {
            float a, b;
            upk2(H0, a, b); *(u64*)(sH + 0 * 68 + c0) = pk2(ssp(a), ssp(b));
            upk2(H1, a, b); *(u64*)(sH + 1 * 68 + c0) = pk2(ssp(a), ssp(b));
            upk2(H2, a, b); *(u64*)(sH + 2 * 68 + c0) = pk2(ssp(a), ssp(b));
            upk2(H3, a, b); *(u64*)(sH + 3 * 68 + c0) = pk2(ssp(a), ssp(b));
        }
        __syncwarp();

        // fr GEMM (64 -> 64); F stays in registers
        u64 F0 = pk2(0.f, 0.f), F1 = F0, F2 = F0, F3 = F0;
#pragma unroll 4
        for (int kk = 0; kk < 64; kk += 4) {
            float4 h0 = *(const float4*)(sH + 0 * 68 + kk);
            float4 h1 = *(const float4*)(sH + 1 * 68 + kk);
            float4 h2 = *(const float4*)(sH + 2 * 68 + kk);
            float4 h3 = *(const float4*)(sH + 3 * 68 + kk);
            u64 w0 = *(const u64*)(sW2 + (kk + 0) * 64 + c0);
            u64 w1 = *(const u64*)(sW2 + (kk + 1) * 64 + c0);
            u64 w2 = *(const u64*)(sW2 + (kk + 2) * 64 + c0);
            u64 w3 = *(const u64*)(sW2 + (kk + 3) * 64 + c0);
            F0 = fma2_(pk2(h0.x, h0.x), w0, F0);
            F1 = fma2_(pk2(h1.x, h1.x), w0, F1);
            F2 = fma2_(pk2(h2.x, h2.x), w0, F2);
            F3 = fma2_(pk2(h3.x, h3.x), w0, F3);
            F0 = fma2_(pk2(h0.y, h0.y), w1, F0);
            F1 = fma2_(pk2(h1.y, h1.y), w1, F1);
            F2 = fma2_(pk2(h2.y, h2.y), w1, F2);
            F3 = fma2_(pk2(h3.y, h3.y), w1, F3);
            F0 = fma2_(pk2(h0.z, h0.z), w2, F0);
            F1 = fma2_(pk2(h1.z, h1.z), w2, F1);
            F2 = fma2_(pk2(h2.z, h2.z), w2, F2);
            F3 = fma2_(pk2(h3.z, h3.z), w2, F3);
            F0 = fma2_(pk2(h0.w, h0.w), w3, F0);
            F1 = fma2_(pk2(h1.w, h1.w), w3, F1);
            F2 = fma2_(pk2(h2.w, h2.w), w3, F2);
            F3 = fma2_(pk2(h3.w, h3.w), w3, F3);
        }
        if (r0 + 1 >= nact) F1 = pk2(0.f, 0.f);
        if (r0 + 2 >= nact) F2 = pk2(0.f, 0.f);
        if (r0 + 3 >= nact) F3 = pk2(0.f, 0.f);

        COUPLE(ue0, A00, A0y, A0z, A0x, F0);
        COUPLE(ue1, B00, B0y, B0z, B0x, F1);
        COUPLE(ue2, C00, C0y, C0z, C0x, F2);
        COUPLE(ue3, D00, D0y, D0z, D0x, F3);
        __syncwarp();
    }

    float* dst = g_acc + node * 704 + c0;
    *(float2*)(dst + 0)   = make_float2(S0a, S0b);
    *(float2*)(dst + 64)  = make_float2(S1a, S1b);
    *(float2*)(dst + 128) = make_float2(U0a, U0b);
    *(float2*)(dst + 192) = make_float2(U1a, U1b);
    *(float2*)(dst + 256) = make_float2(U2a, U2b);
    *(float2*)(dst + 320) = make_float2(P0a, P0b);
    *(float2*)(dst + 384) = make_float2(P1a, P1b);
    *(float2*)(dst + 448) = make_float2(P2a, P2b);
    *(float2*)(dst + 512) = make_float2(Q0a, Q0b);
    *(float2*)(dst + 576) = make_float2(Q1a, Q1b);
    *(float2*)(dst + 640) = make_float2(Q2a, Q2b);
}

// ============================================================
// K3: combined w_a GEMMs. Blocks [0,512): l0 path; [512,1024): l1 path.
//     warp = node (8 nodes/block). A via LDG broadcast, weights in smem.
// ============================================================
#define KAG_SMEM (12288 * 4)
__global__ void __launch_bounds__(256) k_ag(const float* __restrict__ wa0,
                                            const float* __restrict__ wa1) {
    extern __shared__ float sW[];
    int t = threadIdx.x, w = t >> 5, c0 = (t & 31) * 2;
    if (blockIdx.x < 512) {
        for (int i = t; i < 2048; i += 256) ((float4*)sW)[i] = ((const float4*)wa0)[i];
        __syncthreads();
        int node = blockIdx.x * 8 + w;
        const float* A = g_acc + node * 704;
        u64 e0 = pk2(0.f, 0.f), e1 = e0;
#pragma unroll 4
        for (int kk = 0; kk < 64; kk += 4) {
            float4 a = *(const float4*)(A + kk);
            float4 b = *(const float4*)(A + 64 + kk);
            e0 = fma2_(pk2(a.x, a.x), *(const u64*)(sW + (kk + 0) * 64 + c0), e0);
            e1 = fma2_(pk2(b.x, b.x), *(const u64*)(sW + (64 + kk + 0) * 64 + c0), e1);
            e0 = fma2_(pk2(a.y, a.y), *(const u64*)(sW + (kk + 1) * 64 + c0), e0);
            e1 = fma2_(pk2(b.y, b.y), *(const u64*)(sW + (64 + kk + 1) * 64 + c0), e1);
            e0 = fma2_(pk2(a.z, a.z), *(const u64*)(sW + (kk + 2) * 64 + c0), e0);
            e1 = fma2_(pk2(b.z, b.z), *(const u64*)(sW + (64 + kk + 2) * 64 + c0), e1);
            e0 = fma2_(pk2(a.w, a.w), *(const u64*)(sW + (kk + 3) * 64 + c0), e0);
            e1 = fma2_(pk2(b.w, b.w), *(const u64*)(sW + (64 + kk + 3) * 64 + c0), e1);
        }
        float xa, xb, ya, yb;
        upk2(e0, xa, xb);
        upk2(e1, ya, yb);
        *(float2*)(g_agg + node * 256 + c0) = make_float2(xa + ya, xb + yb);
    } else {
        for (int i = t; i < 3072; i += 256) ((float4*)sW)[i] = ((const float4*)wa1)[i];
        __syncthreads();
        int node = (blockIdx.x - 512) * 8 + w;
        u64 m0 = pk2(0.f, 0.f), m1 = m0, m2 = m0;
#pragma unroll
        for (int s = 0; s < 3; s++) {
            const float* A = g_acc + node * 704 + 128 + s * 192;
            const float* ws = sW + s * 4096;
#pragma unroll 4
            for (int kk = 0; kk < 64; kk += 4) {
                float4 a0 = *(const float4*)(A + kk);
                float4 a1 = *(const float4*)(A + 64 + kk);
                float4 a2 = *(const float4*)(A + 128 + kk);
                u64 w0 = *(const u64*)(ws + (kk + 0) * 64 + c0);
                u64 w1 = *(const u64*)(ws + (kk + 1) * 64 + c0);
                u64 w2 = *(const u64*)(ws + (kk + 2) * 64 + c0);
                u64 w3 = *(const u64*)(ws + (kk + 3) * 64 + c0);
                m0 = fma2_(pk2(a0.x, a0.x), w0, m0);
                m1 = fma2_(pk2(a1.x, a1.x), w0, m1);
                m2 = fma2_(pk2(a2.x, a2.x), w0, m2);
                m0 = fma2_(pk2(a0.y, a0.y), w1, m0);
                m1 = fma2_(pk2(a1.y, a1.y), w1, m1);
                m2 = fma2_(pk2(a2.y, a2.y), w1, m2);
                m0 = fma2_(pk2(a0.z, a0.z), w2, m0);
                m1 = fma2_(pk2(a1.z, a1.z), w2, m1);
                m2 = fma2_(pk2(a2.z, a2.z), w2, m2);
                m0 = fma2_(pk2(a0.w, a0.w), w3, m0);
                m1 = fma2_(pk2(a1.w, a1.w), w3, m1);
                m2 = fma2_(pk2(a2.w, a2.w), w3, m2);
            }
        }
        *(u64*)(g_agg + node * 256 + 64 + c0) = m0;
        *(u64*)(g_agg + node * 256 + 128 + c0) = m1;
        *(u64*)(g_agg + node * 256 + 192 + c0) = m2;
    }
}

// ============================================================
// K4: gate + w_b ielin + residual. 8 nodes/block, grid 512.
// ============================================================
#define KFN_SMEM ((4096 + 4096 + 2048 + 64 * 36) * 4)
__global__ void __launch_bounds__(256) k_fin(const float* __restrict__ feat,
                                             const float* __restrict__ wb0,
                                             const float* __restrict__ wb1,
                                             float* __restrict__ out) {
    extern __shared__ float sm[];
    float* sW0 = sm;
    float* sW1 = sm + 4096;
    float* sAg = sm + 8192;   // raw agg 8x256
    float* sAt = sm + 10240;  // gated transposed [k64][row32], stride 36
    int t = threadIdx.x;
    for (int i = t; i < 1024; i += 256) {
        ((float4*)sW0)[i] = ((const float4*)wb0)[i];
        ((float4*)sW1)[i] = ((const float4*)wb1)[i];
    }
    int nodeBase = blockIdx.x * 8;
    for (int i = t; i < 512; i += 256)
        ((float4*)sAg)[i] = *((const float4*)(g_agg + nodeBase * 256) + i);
    __syncthreads();
    for (int i = t; i < 512; i += 256) {
        int nl = i >> 6, c = i & 63;
        const float* a = sAg + nl * 256;
        float a0 = a[c], v1 = a[64 + c], v2 = a[128 + c], v3 = a[192 + c];
        float gt0 = ssp(a0);
        float gt1 = ssp(sqrtf(v1 * v1 + v2 * v2 + v3 * v3 + 1e-12f));
        int row = nl * 4;
        sAt[c * 36 + row] = a0 * gt0;
        sAt[c * 36 + row + 1] = v1 * gt1;
        sAt[c * 36 + row + 2] = v2 * gt1;
        sAt[c * 36 + row + 3] = v3 * gt1;
    }
    __syncthreads();
    int rg = t >> 5, c0 = (t & 31) * 2;
    u64 acc0 = pk2(0.f, 0.f), acc1 = acc0, acc2 = acc0, acc3 = acc0;
#pragma unroll 4
    for (int k = 0; k < 64; k++) {
        float4 a = *(const float4*)(sAt + k * 36 + rg * 4);
        u64 w0 = *(const u64*)(sW0 + k * 64 + c0);
        u64 w1 = *(const u64*)(sW1 + k * 64 + c0);
        acc0 = fma2_(pk2(a.x, a.x), w0, acc0);
        acc1 = fma2_(pk2(a.y, a.y), w1, acc1);
        acc2 = fma2_(pk2(a.z, a.z), w1, acc2);
        acc3 = fma2_(pk2(a.w, a.w), w1, acc3);
    }
    int node = nodeBase + rg;
    u64 av[4] = {acc0, acc1, acc2, acc3};
#pragma unroll
    for (int jj = 0; jj < 4; jj++) {
        int idx = node * 256 + jj * 64 + c0;
        float2 fv = *(const float2*)(feat + idx);
        float oa, ob;
        upk2(av[jj], oa, ob);
        *(float2*)(out + idx) = make_float2(fv.x + oa, fv.y + ob);
    }
}

// ============================================================
extern "C" void kernel_launch(void* const* d_in, const int* in_sizes, int n_in,
                              void* d_out, int out_size) {
    const float* xyz = (const float*)d_in[0];
    const float* feat = (const float*)d_in[1];
    const float* wf1 = (const float*)d_in[2];
    const float* wf2 = (const float*)d_in[3];
    const float* wp0 = (const float*)d_in[4];
    const float* wp1 = (const float*)d_in[5];
    const float* wa0 = (const float*)d_in[6];
    const float* wa1 = (const float*)d_in[7];
    const float* wb0 = (const float*)d_in[8];
    const float* wb1 = (const float*)d_in[9];
    const int* src = (const int*)d_in[10];
    const int* emask = (const int*)d_in[11];
    float* out = (float*)d_out;

    cudaFuncSetAttribute(k_pre, cudaFuncAttributeMaxDynamicSharedMemorySize, KP_SMEM);
    cudaFuncSetAttribute(k_edge, cudaFuncAttributeMaxDynamicSharedMemorySize, KE_SMEM);
    cudaFuncSetAttribute(k_ag, cudaFuncAttributeMaxDynamicSharedMemorySize, KAG_SMEM);
    cudaFuncSetAttribute(k_fin, cudaFuncAttributeMaxDynamicSharedMemorySize, KFN_SMEM);

    k_pre<<<512, 256, KP_SMEM>>>(feat, wp0, wp1);
    k_edge<<<NN / KE_WARPS, 256, KE_SMEM>>>(xyz, wf1, wf2, src, emask);
    k_ag<<<1024, 256, KAG_SMEM>>>(wa0, wa1);
    k_fin<<<512, 256, KFN_SMEM>>>(feat, wb0, wb1, out);
}